// round 12
// baseline (speedup 1.0000x reference)
#include <cuda_runtime.h>
#include <cuda_bf16.h>
#include <cuda_fp16.h>
#include <cstdint>
#include <cstddef>

static constexpr int Bn = 8;
static constexpr int Cc = 512;
static constexpr int Nn = 4096;   // H*W
static constexpr int Kd = 64;
static constexpr int Vd = 512;

// Scratch (device globals)
__device__ __nv_bfloat16 g_Xh[(size_t)Bn * Nn * Cc];   // x transposed [b][n][c] bf16 hi
__device__ __nv_bfloat16 g_Xl[(size_t)Bn * Nn * Cc];
__device__ __half        g_Xf[(size_t)Bn * Nn * Cc];   // x transposed [b][n][c] fp16
__device__ __nv_bfloat16 g_Wh[128 * Cc];               // [Wq;Wk]
__device__ __nv_bfloat16 g_Wl[128 * Cc];
__device__ __half        g_Wvf[Vd * Cc];               // Wv fp16 [v][c]
__device__ __nv_bfloat16 g_Qh[(size_t)Bn * Nn * Kd];
__device__ __nv_bfloat16 g_Ql[(size_t)Bn * Nn * Kd];
__device__ __nv_bfloat16 g_Kh[(size_t)Bn * Nn * Kd];
__device__ __nv_bfloat16 g_Kl[(size_t)Bn * Nn * Kd];
// V fp16 packed as av B-fragments: per [b][mt 0..63]: [kb 0..3][vj 0..63][lane][2] u32
__device__ uint32_t g_Vh[(size_t)Bn * 64 * 16384];
// P fp16 packed as av A-fragments: per [b][nt 0..31][mt 0..63]:
//   [i_blk 0..7][kb 0..3][lane 0..31][4] u32   (4096 u32 = 16KB per tile)
__device__ uint32_t g_Pf[(size_t)Bn * 32 * 64 * 4096];
__device__ float g_M [(size_t)Bn * Nn];        // row maxes (approx)
__device__ float g_L [(size_t)Bn * Nn];        // row sums of shifted exps
__device__ float g_scl[Vd];
__device__ float g_shf[Vd];

// ===========================================================================
// Helpers (portable ISA: sm_80-class mma.sync + cp.async only)
// ===========================================================================
__device__ __forceinline__ uint32_t smem_u32(const void* p) {
    uint32_t a;
    asm("{ .reg .u64 t; cvta.to.shared.u64 t, %1; cvt.u32.u64 %0, t; }" : "=r"(a) : "l"(p));
    return a;
}
__device__ __forceinline__ void cp_async16(uint32_t saddr, const void* gaddr) {
    asm volatile("cp.async.ca.shared.global [%0], [%1], 16;"
                 :: "r"(saddr), "l"(gaddr) : "memory");
}
__device__ __forceinline__ void cp_commit() {
    asm volatile("cp.async.commit_group;" ::: "memory");
}
__device__ __forceinline__ void cp_wait1() {
    asm volatile("cp.async.wait_group 1;" ::: "memory");
}
__device__ __forceinline__ void cp_wait0() {
    asm volatile("cp.async.wait_group 0;" ::: "memory");
}
__device__ __forceinline__ void mma_bf16(float* d, const uint32_t* a, const uint32_t* b) {
    asm volatile(
        "mma.sync.aligned.m16n8k16.row.col.f32.bf16.bf16.f32 "
        "{%0,%1,%2,%3}, {%4,%5,%6,%7}, {%8,%9}, {%0,%1,%2,%3};"
        : "+f"(d[0]), "+f"(d[1]), "+f"(d[2]), "+f"(d[3])
        : "r"(a[0]), "r"(a[1]), "r"(a[2]), "r"(a[3]), "r"(b[0]), "r"(b[1]));
}
__device__ __forceinline__ void mma_f16(float* d, const uint32_t* a, const uint32_t* b) {
    asm volatile(
        "mma.sync.aligned.m16n8k16.row.col.f32.f16.f16.f32 "
        "{%0,%1,%2,%3}, {%4,%5,%6,%7}, {%8,%9}, {%0,%1,%2,%3};"
        : "+f"(d[0]), "+f"(d[1]), "+f"(d[2]), "+f"(d[3])
        : "r"(a[0]), "r"(a[1]), "r"(a[2]), "r"(a[3]), "r"(b[0]), "r"(b[1]));
}
__device__ __forceinline__ uint32_t lds_u32(const char* p) { return *(const uint32_t*)p; }
__device__ __forceinline__ uint32_t bfcat(__nv_bfloat16 lo, __nv_bfloat16 hi) {
    __nv_bfloat162 t; t.x = lo; t.y = hi;
    return *(uint32_t*)&t;
}
__device__ __forceinline__ uint32_t hfcat(__half lo, __half hi) {
    __half2 t; t.x = lo; t.y = hi;
    return *(uint32_t*)&t;
}

// ===========================================================================
// BN scale/shift precompute
// ===========================================================================
__global__ void prep_kernel(const float* __restrict__ gamma, const float* __restrict__ beta,
                            const float* __restrict__ mean,  const float* __restrict__ var) {
    int i = threadIdx.x;
    if (i < Vd) {
        float s = gamma[i] * rsqrtf(var[i] + 1e-5f);
        g_scl[i] = s;
        g_shf[i] = beta[i] - mean[i] * s;
    }
}

// ===========================================================================
// W split: [Wq;Wk] -> bf16 hi/lo
// ===========================================================================
__global__ __launch_bounds__(256) void wsplit_kernel(const float* __restrict__ Wq,
                                                     const float* __restrict__ Wk) {
    int id = blockIdx.x * 256 + threadIdx.x;
    int o = id >> 9, cc = id & 511;
    float v = (o < 64) ? Wq[o * Cc + cc] : Wk[(o - 64) * Cc + cc];
    __nv_bfloat16 h = __float2bfloat16(v);
    g_Wh[id] = h;
    g_Wl[id] = __float2bfloat16(v - __bfloat162float(h));
}

// ===========================================================================
// Wv -> fp16
// ===========================================================================
__global__ __launch_bounds__(256) void wvhalf_kernel(const float* __restrict__ Wv) {
    int id = blockIdx.x * 256 + threadIdx.x;     // 512*512
    g_Wvf[id] = __float2half(Wv[id]);
}

// ===========================================================================
// X split + transpose: x[b][c][n] fp32 -> [b][n][c]: bf16 hi/lo + fp16
// ===========================================================================
__global__ __launch_bounds__(256) void xsplit_kernel(const float* __restrict__ x) {
    __shared__ float t[32][33];
    const int b = blockIdx.z, n0 = blockIdx.x * 32, c0 = blockIdx.y * 32;
    const int tx = threadIdx.x & 31, ty = threadIdx.x >> 5;
    #pragma unroll
    for (int p = 0; p < 4; p++)
        t[ty + 8 * p][tx] = x[((size_t)b * Cc + c0 + ty + 8 * p) * Nn + n0 + tx];
    __syncthreads();
    #pragma unroll
    for (int p = 0; p < 4; p++) {
        float v = t[tx][ty + 8 * p];
        __nv_bfloat16 h = __float2bfloat16(v);
        __nv_bfloat16 l = __float2bfloat16(v - __bfloat162float(h));
        size_t idx = ((size_t)b * Nn + n0 + ty + 8 * p) * Cc + c0 + tx;
        g_Xh[idx] = h;
        g_Xl[idx] = l;
        g_Xf[idx] = __float2half(v);
    }
}

// ===========================================================================
// Q+K projection on mma.sync bf16 (3-term split)   (unchanged)
// ===========================================================================
static constexpr int QK_XH0 = 0,     QK_XH1 = 5120;
static constexpr int QK_XL0 = 10240, QK_XL1 = 15360;
static constexpr int QK_WH0 = 20480, QK_WH1 = 30720;
static constexpr int QK_WL0 = 40960, QK_WL1 = 51200;
static constexpr int QK_BYTES = 61440;

__device__ __forceinline__ void qk_stage(uint32_t sbase, int buf, int b, int n0, int kc) {
    const int t = threadIdx.x;
    const uint32_t xh = sbase + (buf ? QK_XH1 : QK_XH0);
    const uint32_t xl = sbase + (buf ? QK_XL1 : QK_XL0);
    const uint32_t wh = sbase + (buf ? QK_WH1 : QK_WH0);
    const uint32_t wl = sbase + (buf ? QK_WL1 : QK_WL0);
    {
        int r = t >> 2, c4 = t & 3;
        size_t src = ((size_t)b * Nn + n0 + r) * Cc + kc * 32 + c4 * 8;
        cp_async16(xh + r * 80 + c4 * 16, g_Xh + src);
        cp_async16(xl + r * 80 + c4 * 16, g_Xl + src);
    }
    #pragma unroll
    for (int p = 0; p < 2; p++) {
        int id = t + 256 * p, r = id >> 2, c4 = id & 3;
        size_t src = (size_t)r * Cc + kc * 32 + c4 * 8;
        cp_async16(wh + r * 80 + c4 * 16, g_Wh + src);
        cp_async16(wl + r * 80 + c4 * 16, g_Wl + src);
    }
}

__global__ __launch_bounds__(256) void qk_mma_kernel(const float* __restrict__ bq,
                                                     const float* __restrict__ bk) {
    extern __shared__ char smc[];
    const uint32_t sbase = smem_u32(smc);
    const int tid = threadIdx.x;
    const int wid = tid >> 5, lane = tid & 31;
    const int g = lane >> 2, c = lane & 3;
    const int wn = wid & 1, wo = wid >> 1;
    const int b  = blockIdx.z;
    const int n0 = blockIdx.x * 64;

    float acc[2][4][4] = {};

    qk_stage(sbase, 0, b, n0, 0);
    cp_commit();

    for (int kc = 0; kc < 16; kc++) {
        const int cur = kc & 1;
        if (kc + 1 < 16) {
            qk_stage(sbase, cur ^ 1, b, n0, kc + 1);
            cp_commit();
            cp_wait1();
        } else {
            cp_wait0();
        }
        __syncthreads();

        const char* XH = smc + (cur ? QK_XH1 : QK_XH0);
        const char* XL = smc + (cur ? QK_XL1 : QK_XL0);
        const char* WH = smc + (cur ? QK_WH1 : QK_WH0);
        const char* WL = smc + (cur ? QK_WL1 : QK_WL0);

        #pragma unroll
        for (int ks = 0; ks < 2; ks++) {
            uint32_t ah[2][4], al[2][4];
            #pragma unroll
            for (int i = 0; i < 2; i++) {
                const int off = (wn * 32 + i * 16 + g) * 80 + ks * 32 + c * 4;
                ah[i][0] = lds_u32(XH + off);
                ah[i][1] = lds_u32(XH + off + 8 * 80);
                ah[i][2] = lds_u32(XH + off + 16);
                ah[i][3] = lds_u32(XH + off + 8 * 80 + 16);
                al[i][0] = lds_u32(XL + off);
                al[i][1] = lds_u32(XL + off + 8 * 80);
                al[i][2] = lds_u32(XL + off + 16);
                al[i][3] = lds_u32(XL + off + 8 * 80 + 16);
            }
            uint32_t bh[4][2], bl[4][2];
            #pragma unroll
            for (int j = 0; j < 4; j++) {
                const int off = (wo * 32 + j * 8 + g) * 80 + ks * 32 + c * 4;
                bh[j][0] = lds_u32(WH + off);
                bh[j][1] = lds_u32(WH + off + 16);
                bl[j][0] = lds_u32(WL + off);
                bl[j][1] = lds_u32(WL + off + 16);
            }
            #pragma unroll
            for (int i = 0; i < 2; i++)
                #pragma unroll
                for (int j = 0; j < 4; j++) {
                    mma_bf16(acc[i][j], ah[i], bh[j]);
                    mma_bf16(acc[i][j], ah[i], bl[j]);
                    mma_bf16(acc[i][j], al[i], bh[j]);
                }
        }
        __syncthreads();
    }

    const int which = wo >> 1;
    __nv_bfloat16* dh = which ? g_Kh : g_Qh;
    __nv_bfloat16* dl = which ? g_Kl : g_Ql;
    const float* bias = which ? bk : bq;
    #pragma unroll
    for (int i = 0; i < 2; i++) {
        const int n_lo = n0 + wn * 32 + i * 16 + g;
        #pragma unroll
        for (int j = 0; j < 4; j++) {
            const int o = (wo * 32 + j * 8 + 2 * c) & 63;
            const float b0 = bias[o], b1 = bias[o + 1];
            float v00 = acc[i][j][0] + b0, v01 = acc[i][j][1] + b1;
            float v10 = acc[i][j][2] + b0, v11 = acc[i][j][3] + b1;
            __nv_bfloat16 h00 = __float2bfloat16(v00), h01 = __float2bfloat16(v01);
            __nv_bfloat16 h10 = __float2bfloat16(v10), h11 = __float2bfloat16(v11);
            __nv_bfloat16 l00 = __float2bfloat16(v00 - __bfloat162float(h00));
            __nv_bfloat16 l01 = __float2bfloat16(v01 - __bfloat162float(h01));
            __nv_bfloat16 l10 = __float2bfloat16(v10 - __bfloat162float(h10));
            __nv_bfloat16 l11 = __float2bfloat16(v11 - __bfloat162float(h11));
            size_t r0 = ((size_t)b * Nn + n_lo) * Kd + o;
            size_t r1 = ((size_t)b * Nn + n_lo + 8) * Kd + o;
            *(uint32_t*)&dh[r0] = bfcat(h00, h01);
            *(uint32_t*)&dh[r1] = bfcat(h10, h11);
            *(uint32_t*)&dl[r0] = bfcat(l00, l01);
            *(uint32_t*)&dl[r1] = bfcat(l10, l11);
        }
    }
}

// ===========================================================================
// Max pass: M[b][n] ~= max_m (q.k) via hi-only bf16 QK^T.   (unchanged)
// ===========================================================================
static constexpr int MX_QH  = 0;
static constexpr int MX_KH0 = 9216;
static constexpr int MX_KH1 = 18432;
static constexpr int MX_BYTES = 27648;

__global__ __launch_bounds__(256) void maxpass_kernel() {
    extern __shared__ char smc[];
    __shared__ float sM[4][64];
    const uint32_t sbase = smem_u32(smc);
    const int tid = threadIdx.x;
    const int wid = tid >> 5, lane = tid & 31;
    const int g = lane >> 2, c = lane & 3;
    const int wn = wid & 1, wv = wid >> 1;
    const int b  = blockIdx.y;
    const int n0 = blockIdx.x * 64;

    const size_t qoff = ((size_t)b * Nn + n0) * Kd;
    const size_t koff = (size_t)b * Nn * Kd;

    #pragma unroll
    for (int p = 0; p < 2; p++) {
        int id = tid + 256 * p, r = id >> 3, c8 = id & 7;
        cp_async16(sbase + MX_QH + r * 144 + c8 * 16, g_Qh + qoff + (size_t)r * Kd + c8 * 8);
    }
    {
        int r = tid >> 2, c8 = (tid & 3) * 2;
        cp_async16(sbase + MX_KH0 + r * 144 + c8 * 16, g_Kh + koff + (size_t)r * Kd + c8 * 8);
        cp_async16(sbase + MX_KH0 + r * 144 + (c8 + 1) * 16, g_Kh + koff + (size_t)r * Kd + (c8 + 1) * 8);
    }
    cp_commit();

    float mx[2][2] = { { -1e30f, -1e30f }, { -1e30f, -1e30f } };

    for (int mc = 0; mc < 64; mc++) {
        const int cur = mc & 1;
        if (mc + 1 < 64) {
            const uint32_t kh = sbase + ((mc + 1) & 1 ? MX_KH1 : MX_KH0);
            int r = tid >> 2, c8 = (tid & 3) * 2;
            cp_async16(kh + r * 144 + c8 * 16,
                       g_Kh + koff + (size_t)((mc + 1) * 64 + r) * Kd + c8 * 8);
            cp_async16(kh + r * 144 + (c8 + 1) * 16,
                       g_Kh + koff + (size_t)((mc + 1) * 64 + r) * Kd + (c8 + 1) * 8);
            cp_commit();
            cp_wait1();
        } else {
            cp_wait0();
        }
        __syncthreads();

        const char* QH = smc + MX_QH;
        const char* KH = smc + (cur ? MX_KH1 : MX_KH0);

        float acc[2][2][4] = {};
        #pragma unroll
        for (int ks = 0; ks < 4; ks++) {
            uint32_t ah[2][4];
            #pragma unroll
            for (int i = 0; i < 2; i++) {
                const int off = (wn * 32 + i * 16 + g) * 144 + ks * 32 + c * 4;
                ah[i][0] = lds_u32(QH + off);
                ah[i][1] = lds_u32(QH + off + 8 * 144);
                ah[i][2] = lds_u32(QH + off + 16);
                ah[i][3] = lds_u32(QH + off + 8 * 144 + 16);
            }
            uint32_t bh[2][2];
            #pragma unroll
            for (int j = 0; j < 2; j++) {
                const int off = (wv * 16 + j * 8 + g) * 144 + ks * 32 + c * 4;
                bh[j][0] = lds_u32(KH + off);
                bh[j][1] = lds_u32(KH + off + 16);
            }
            #pragma unroll
            for (int i = 0; i < 2; i++)
                #pragma unroll
                for (int j = 0; j < 2; j++)
                    mma_bf16(acc[i][j], ah[i], bh[j]);
        }
        __syncthreads();

        #pragma unroll
        for (int i = 0; i < 2; i++)
            #pragma unroll
            for (int j = 0; j < 2; j++) {
                mx[i][0] = fmaxf(mx[i][0], fmaxf(acc[i][j][0], acc[i][j][1]));
                mx[i][1] = fmaxf(mx[i][1], fmaxf(acc[i][j][2], acc[i][j][3]));
            }
    }

    #pragma unroll
    for (int i = 0; i < 2; i++)
        #pragma unroll
        for (int r = 0; r < 2; r++) {
            float v = mx[i][r];
            v = fmaxf(v, __shfl_xor_sync(0xffffffffu, v, 1));
            v = fmaxf(v, __shfl_xor_sync(0xffffffffu, v, 2));
            mx[i][r] = v;
        }
    if (c == 0) {
        #pragma unroll
        for (int i = 0; i < 2; i++) {
            sM[wv][wn * 32 + i * 16 + g]     = mx[i][0];
            sM[wv][wn * 32 + i * 16 + g + 8] = mx[i][1];
        }
    }
    __syncthreads();
    if (tid < 64)
        g_M[(size_t)b * Nn + n0 + tid] =
            fmaxf(fmaxf(sM[0][tid], sM[1][tid]), fmaxf(sM[2][tid], sM[3][tid]));
}

// ===========================================================================
// V projection on single-pass fp16 mma.sync   (unchanged)
// ===========================================================================
static constexpr int VP_W0 = 0,     VP_W1 = 10240;
static constexpr int VP_X0 = 20480, VP_X1 = 30720;
static constexpr int VP_BYTES = 40960;

__device__ __forceinline__ void vproj_stage(uint32_t sbase, int buf, int b,
                                            int m0, int v0, int kc) {
    const int t = threadIdx.x;
    const uint32_t sW = sbase + (buf ? VP_W1 : VP_W0);
    const uint32_t sX = sbase + (buf ? VP_X1 : VP_X0);
    #pragma unroll
    for (int p = 0; p < 2; p++) {
        int id = t + 256 * p, r = id >> 2, c4 = id & 3;
        cp_async16(sW + r * 80 + c4 * 16,
                   g_Wvf + (size_t)(v0 + r) * Cc + kc * 32 + c4 * 8);
    }
    #pragma unroll
    for (int p = 0; p < 2; p++) {
        int id = t + 256 * p, r = id >> 2, c4 = id & 3;
        cp_async16(sX + r * 80 + c4 * 16,
                   g_Xf + ((size_t)b * Nn + m0 + r) * Cc + kc * 32 + c4 * 8);
    }
}

__global__ __launch_bounds__(256) void vproj_mma_kernel() {
    extern __shared__ char smc[];
    const uint32_t sbase = smem_u32(smc);
    const int tid = threadIdx.x;
    const int wid = tid >> 5, lane = tid & 31;
    const int g = lane >> 2, c = lane & 3;
    const int wn = wid & 1, wv = wid >> 1;
    const int b  = blockIdx.z;
    const int m0 = blockIdx.y * 128;
    const int v0 = blockIdx.x * 128;

    float acc[4][4][4] = {};

    vproj_stage(sbase, 0, b, m0, v0, 0);
    cp_commit();

    for (int kc = 0; kc < Cc / 32; kc++) {
        const int cur = kc & 1;
        if (kc + 1 < Cc / 32) {
            vproj_stage(sbase, cur ^ 1, b, m0, v0, kc + 1);
            cp_commit();
            cp_wait1();
        } else {
            cp_wait0();
        }
        __syncthreads();

        const char* Ws = smc + (cur ? VP_W1 : VP_W0);
        const char* Xs = smc + (cur ? VP_X1 : VP_X0);

        #pragma unroll
        for (int ks = 0; ks < 2; ks++) {
            uint32_t af[4][4];
            #pragma unroll
            for (int i = 0; i < 4; i++) {
                const int off = (wn * 64 + i * 16 + g) * 80 + ks * 32 + c * 4;
                af[i][0] = lds_u32(Ws + off);
                af[i][1] = lds_u32(Ws + off + 8 * 80);
                af[i][2] = lds_u32(Ws + off + 16);
                af[i][3] = lds_u32(Ws + off + 8 * 80 + 16);
            }
            uint32_t bf[4][2];
            #pragma unroll
            for (int j = 0; j < 4; j++) {
                const int off = (wv * 32 + j * 8 + g) * 80 + ks * 32 + c * 4;
                bf[j][0] = lds_u32(Xs + off);
                bf[j][1] = lds_u32(Xs + off + 16);
            }
            #pragma unroll
            for (int i = 0; i < 4; i++)
                #pragma unroll
                for (int j = 0; j < 4; j++)
                    mma_f16(acc[i][j], af[i], bf[j]);
        }
        __syncthreads();
    }

    const int mt = blockIdx.y * 2 + (wv >> 1);
    uint32_t* base = g_Vh + ((size_t)b * 64 + mt) * 16384;
    #pragma unroll
    for (int i = 0; i < 4; i++) {
        const int vg = v0 + wn * 64 + i * 16 + g;
        const float sg = g_scl[vg],     hg = g_shf[vg];
        const float s8 = g_scl[vg + 8], h8 = g_shf[vg + 8];
        const int vj = vg >> 3;
        #pragma unroll
        for (int j = 0; j < 4; j++) {
            const int kb = ((wv * 32 + j * 8) >> 4) & 3;
            const int lohi = j & 1;
            __half a0 = __float2half(fmaxf(fmaf(acc[i][j][0], sg, hg), 0.f));
            __half a1 = __float2half(fmaxf(fmaf(acc[i][j][1], sg, hg), 0.f));
            __half a2 = __float2half(fmaxf(fmaf(acc[i][j][2], s8, h8), 0.f));
            __half a3 = __float2half(fmaxf(fmaf(acc[i][j][3], s8, h8), 0.f));
            base[(size_t)kb * 4096 + (size_t)vj * 64 + lane * 2 + lohi]       = hfcat(a0, a1);
            base[(size_t)kb * 4096 + (size_t)(vj + 1) * 64 + lane * 2 + lohi] = hfcat(a2, a3);
        }
    }
}

// ===========================================================================
// Energy on mma.sync BF16 (3-term); epilogue exp(l-M) -> fp16 A-frags (unchanged)
// ===========================================================================
static constexpr int E_QH  = 0;
static constexpr int E_QL  = 9216;
static constexpr int E_KH0 = 18432;
static constexpr int E_KH1 = 27648;
static constexpr int E_KL0 = 36864;
static constexpr int E_KL1 = 46080;
static constexpr int E_BYTES = 55296;

__global__ __launch_bounds__(256) void energy_mma_kernel() {
    extern __shared__ char smc[];
    __shared__ float sL[4][64];
    const uint32_t sbase = smem_u32(smc);
    const int tid = threadIdx.x;
    const int wid = tid >> 5, lane = tid & 31;
    const int g = lane >> 2, c = lane & 3;
    const int wn = wid & 1, wv = wid >> 1;
    const int b  = blockIdx.y;
    const int n0 = blockIdx.x * 64;
    const int nt = blockIdx.x >> 1;
    const int half = blockIdx.x & 1;

    const size_t qoff = ((size_t)b * Nn + n0) * Kd;
    const size_t koff = (size_t)b * Nn * Kd;

    #pragma unroll
    for (int p = 0; p < 2; p++) {
        int id = tid + 256 * p, r = id >> 3, c8 = id & 7;
        cp_async16(sbase + E_QH + r * 144 + c8 * 16, g_Qh + qoff + (size_t)r * Kd + c8 * 8);
        cp_async16(sbase + E_QL + r * 144 + c8 * 16, g_Ql + qoff + (size_t)r * Kd + c8 * 8);
    }
    #pragma unroll
    for (int p = 0; p < 2; p++) {
        int id = tid + 256 * p, r = id >> 3, c8 = id & 7;
        cp_async16(sbase + E_KH0 + r * 144 + c8 * 16, g_Kh + koff + (size_t)r * Kd + c8 * 8);
        cp_async16(sbase + E_KL0 + r * 144 + c8 * 16, g_Kl + koff + (size_t)r * Kd + c8 * 8);
    }
    cp_commit();

    float Mv[2][2];
    #pragma unroll
    for (int i = 0; i < 2; i++) {
        Mv[i][0] = g_M[(size_t)b * Nn + n0 + wn * 32 + i * 16 + g];
        Mv[i][1] = g_M[(size_t)b * Nn + n0 + wn * 32 + i * 16 + g + 8];
    }

    float rsum[2][2] = {};

    for (int mc = 0; mc < 64; mc++) {
        const int cur = mc & 1;
        if (mc + 1 < 64) {
            const uint32_t kh = sbase + ((mc + 1) & 1 ? E_KH1 : E_KH0);
            const uint32_t kl = sbase + ((mc + 1) & 1 ? E_KL1 : E_KL0);
            #pragma unroll
            for (int p = 0; p < 2; p++) {
                int id = tid + 256 * p, r = id >> 3, c8 = id & 7;
                cp_async16(kh + r * 144 + c8 * 16,
                           g_Kh + koff + (size_t)((mc + 1) * 64 + r) * Kd + c8 * 8);
                cp_async16(kl + r * 144 + c8 * 16,
                           g_Kl + koff + (size_t)((mc + 1) * 64 + r) * Kd + c8 * 8);
            }
            cp_commit();
            cp_wait1();
        } else {
            cp_wait0();
        }
        __syncthreads();

        const char* QH = smc + E_QH;
        const char* QL = smc + E_QL;
        const char* KH = smc + (cur ? E_KH1 : E_KH0);
        const char* KL = smc + (cur ? E_KL1 : E_KL0);

        float acc[2][2][4] = {};
        #pragma unroll
        for (int ks = 0; ks < 4; ks++) {
            uint32_t ah[2][4], al[2][4];
            #pragma unroll
            for (int i = 0; i < 2; i++) {
                const int off = (wn * 32 + i * 16 + g) * 144 + ks * 32 + c * 4;
                ah[i][0] = lds_u32(QH + off);
                ah[i][1] = lds_u32(QH + off + 8 * 144);
                ah[i][2] = lds_u32(QH + off + 16);
                ah[i][3] = lds_u32(QH + off + 8 * 144 + 16);
                al[i][0] = lds_u32(QL + off);
                al[i][1] = lds_u32(QL + off + 8 * 144);
                al[i][2] = lds_u32(QL + off + 16);
                al[i][3] = lds_u32(QL + off + 8 * 144 + 16);
            }
            uint32_t bh[2][2], bl[2][2];
            #pragma unroll
            for (int j = 0; j < 2; j++) {
                const int off = (wv * 16 + j * 8 + g) * 144 + ks * 32 + c * 4;
                bh[j][0] = lds_u32(KH + off);
                bh[j][1] = lds_u32(KH + off + 16);
                bl[j][0] = lds_u32(KL + off);
                bl[j][1] = lds_u32(KL + off + 16);
            }
            #pragma unroll
            for (int i = 0; i < 2; i++)
                #pragma unroll
                for (int j = 0; j < 2; j++) {
                    mma_bf16(acc[i][j], ah[i], bh[j]);
                    mma_bf16(acc[i][j], ah[i], bl[j]);
                    mma_bf16(acc[i][j], al[i], bh[j]);
                }
        }
        __syncthreads();

        const size_t tile0 = (((size_t)b * 32 + nt) * 64 + mc) * 4096;
        #pragma unroll
        for (int i = 0; i < 2; i++) {
            const int i_blk = half * 4 + wn * 2 + i;
            __half h[2][4];
            #pragma unroll
            for (int j = 0; j < 2; j++) {
                h[j][0] = __float2half(__expf(acc[i][j][0] - Mv[i][0]));
                h[j][1] = __float2half(__expf(acc[i][j][1] - Mv[i][0]));
                h[j][2] = __float2half(__expf(acc[i][j][2] - Mv[i][1]));
                h[j][3] = __float2half(__expf(acc[i][j][3] - Mv[i][1]));
                rsum[i][0] += __half2float(h[j][0]) + __half2float(h[j][1]);
                rsum[i][1] += __half2float(h[j][2]) + __half2float(h[j][3]);
            }
            uint4 w4;
            w4.x = hfcat(h[0][0], h[0][1]);
            w4.y = hfcat(h[0][2], h[0][3]);
            w4.z = hfcat(h[1][0], h[1][1]);
            w4.w = hfcat(h[1][2], h[1][3]);
            *(uint4*)&g_Pf[tile0 + (size_t)((i_blk * 4 + wv) * 128 + lane * 4)] = w4;
        }
    }

    #pragma unroll
    for (int i = 0; i < 2; i++)
        #pragma unroll
        for (int r = 0; r < 2; r++) {
            float v = rsum[i][r];
            v += __shfl_xor_sync(0xffffffffu, v, 1);
            v += __shfl_xor_sync(0xffffffffu, v, 2);
            rsum[i][r] = v;
        }
    if (c == 0) {
        #pragma unroll
        for (int i = 0; i < 2; i++) {
            sL[wv][wn * 32 + i * 16 + g]     = rsum[i][0];
            sL[wv][wn * 32 + i * 16 + g + 8] = rsum[i][1];
        }
    }
    __syncthreads();
    if (tid < 64)
        g_L[(size_t)b * Nn + n0 + tid] = sL[0][tid] + sL[1][tid] + sL[2][tid] + sL[3][tid];
}

// ===========================================================================
// PV GEMM on fp16 m16n8k16: A (P stream) via cp.async smem pipeline,
// B (V, L2-resident) via DIRECT LDG.64 with kb-level register prefetch.
// Block 128(n) x 128(v), warp 64x32 (2x4 warps), K-chunk 64 (one mt tile).
// SMEM u32: A stages @ {0, 4096} (16KB each) = 32KB total -> 2 CTAs/SM.
// ===========================================================================
static constexpr int AV_BYTES = 32768;

__device__ __forceinline__ void av_stageA(uint32_t sbase, int buf, const uint32_t* gAt) {
    const int t = threadIdx.x;
    const uint32_t sA = sbase + (buf ? 4096u : 0u) * 4;
    #pragma unroll
    for (int p = 0; p < 4; p++) {
        int id = t + 256 * p;
        cp_async16(sA + (uint32_t)id * 16, gAt + id * 4);
    }
}

__global__ __launch_bounds__(256, 2) void av_mma_kernel(float* __restrict__ out) {
    extern __shared__ uint32_t smu[];
    const uint32_t sbase = smem_u32(smu);
    const int tid  = threadIdx.x;
    const int wid  = tid >> 5, lane = tid & 31;
    const int g = lane >> 2, c = lane & 3;
    const int wn = wid & 1, wv = wid >> 1;
    const int b  = blockIdx.z;
    const int nt = blockIdx.y;
    const int n0 = nt * 128;
    const int v0 = blockIdx.x * 128;

    const uint32_t* gA = g_Pf + (((size_t)b * 32 + nt) * 64) * 4096;
    // per-warp B base: fragment (mt, kb, j) at +mt*16384 + kb*4096 + j*64
    const uint32_t* gBw = g_Vh + (size_t)b * 64 * 16384
                        + (size_t)(v0 >> 3) * 64 + (size_t)(wv * 4) * 64 + lane * 2;

    float acc[4][4][4] = {};
    uint2 bfr[2][4];

    av_stageA(sbase, 0, gA);
    cp_commit();
    #pragma unroll
    for (int j = 0; j < 4; j++)
        bfr[0][j] = *(const uint2*)(gBw + j * 64);   // (mt=0, kb=0)

    for (int mt = 0; mt < 64; mt++) {
        const int cur = mt & 1;
        if (mt + 1 < 64) {
            av_stageA(sbase, cur ^ 1, gA + (size_t)(mt + 1) * 4096);
            cp_commit();
            cp_wait1();
        } else {
            cp_wait0();
        }
        __syncthreads();

        const uint32_t* As = smu + cur * 4096;

        #pragma unroll
        for (int kb = 0; kb < 4; kb++) {
            // prefetch B fragments for next (mt, kb) slot
            const int nmt = (kb == 3) ? mt + 1 : mt;
            const int nkb = (kb == 3) ? 0 : kb + 1;
            if (nmt < 64) {
                const uint32_t* gp = gBw + (size_t)nmt * 16384 + (size_t)nkb * 4096;
                #pragma unroll
                for (int j = 0; j < 4; j++)
                    bfr[(kb + 1) & 1][j] = *(const uint2*)(gp + j * 64);
            }
            uint4 af[4];
            #pragma unroll
            for (int i = 0; i < 4; i++)
                af[i] = *(const uint4*)(As + (wn * 4 + i) * 512 + kb * 128 + lane * 4);
            #pragma unroll
            for (int i = 0; i < 4; i++)
                #pragma unroll
                for (int j = 0; j < 4; j++)
                    mma_f16(acc[i][j], (const uint32_t*)&af[i],
                            (const uint32_t*)&bfr[kb & 1][j]);
        }
        __syncthreads();
    }

    #pragma unroll
    for (int i = 0; i < 4; i++) {
        const int n_lo = n0 + wn * 64 + i * 16 + g;
        const float linv_lo = 1.0f / g_L[(size_t)b * Nn + n_lo];
        const float linv_hi = 1.0f / g_L[(size_t)b * Nn + n_lo + 8];
        #pragma unroll
        for (int j = 0; j < 4; j++) {
            const int v = v0 + wv * 32 + j * 8 + c * 2;
            float* o0p = out + ((size_t)b * Vd + v)     * Nn + n_lo;
            float* o1p = out + ((size_t)b * Vd + v + 1) * Nn + n_lo;
            o0p[0] = acc[i][j][0] * linv_lo;
            o1p[0] = acc[i][j][1] * linv_lo;
            o0p[8] = acc[i][j][2] * linv_hi;
            o1p[8] = acc[i][j][3] * linv_hi;
        }
    }
}

// ===========================================================================
extern "C" void kernel_launch(void* const* d_in, const int* in_sizes, int n_in,
                              void* d_out, int out_size) {
    const float* x     = (const float*)d_in[0];
    const float* Wq    = (const float*)d_in[1];
    const float* bq    = (const float*)d_in[2];
    const float* Wk    = (const float*)d_in[3];
    const float* bk    = (const float*)d_in[4];
    const float* Wv    = (const float*)d_in[5];
    const float* gamma = (const float*)d_in[6];
    const float* beta  = (const float*)d_in[7];
    const float* mean  = (const float*)d_in[8];
    const float* var   = (const float*)d_in[9];
    float* out = (float*)d_out;

    static int smem_set = 0;
    if (!smem_set) {
        cudaFuncSetAttribute(qk_mma_kernel,
                             cudaFuncAttributeMaxDynamicSharedMemorySize, QK_BYTES);
        cudaFuncSetAttribute(maxpass_kernel,
                             cudaFuncAttributeMaxDynamicSharedMemorySize, MX_BYTES);
        cudaFuncSetAttribute(vproj_mma_kernel,
                             cudaFuncAttributeMaxDynamicSharedMemorySize, VP_BYTES);
        cudaFuncSetAttribute(energy_mma_kernel,
                             cudaFuncAttributeMaxDynamicSharedMemorySize, E_BYTES);
        cudaFuncSetAttribute(av_mma_kernel,
                             cudaFuncAttributeMaxDynamicSharedMemorySize, AV_BYTES);
        smem_set = 1;
    }

    prep_kernel<<<1, 512>>>(gamma, beta, mean, var);
    wsplit_kernel<<<256, 256>>>(Wq, Wk);
    wvhalf_kernel<<<1024, 256>>>(Wv);
    xsplit_kernel<<<dim3(Nn / 32, Cc / 32, Bn), 256>>>(x);

    qk_mma_kernel<<<dim3(Nn / 64, 1, Bn), 256, QK_BYTES>>>(bq, bk);
    vproj_mma_kernel<<<dim3(Vd / 128, Nn / 128, Bn), 256, VP_BYTES>>>();

    maxpass_kernel<<<dim3(Nn / 64, Bn), 256, MX_BYTES>>>();
    energy_mma_kernel<<<dim3(Nn / 64, Bn), 256, E_BYTES>>>();

    av_mma_kernel<<<dim3(Vd / 128, Nn / 128, Bn), 256, AV_BYTES>>>(out);
}

// round 14
// speedup vs baseline: 1.0038x; 1.0038x over previous
#include <cuda_runtime.h>
#include <cuda_bf16.h>
#include <cuda_fp16.h>
#include <cstdint>
#include <cstddef>

static constexpr int Bn = 8;
static constexpr int Cc = 512;
static constexpr int Nn = 4096;   // H*W
static constexpr int Kd = 64;
static constexpr int Vd = 512;

// Scratch (device globals)
__device__ __nv_bfloat16 g_Xh[(size_t)Bn * Nn * Cc];   // x transposed [b][n][c] bf16 hi
__device__ __nv_bfloat16 g_Xl[(size_t)Bn * Nn * Cc];
__device__ __half        g_Xf[(size_t)Bn * Nn * Cc];   // x transposed [b][n][c] fp16
__device__ __nv_bfloat16 g_Wh[128 * Cc];               // [Wq;Wk]
__device__ __nv_bfloat16 g_Wl[128 * Cc];
__device__ __half        g_Wvf[Vd * Cc];               // Wv fp16 [v][c]
__device__ __nv_bfloat16 g_Qh[(size_t)Bn * Nn * Kd];
__device__ __nv_bfloat16 g_Ql[(size_t)Bn * Nn * Kd];
__device__ __nv_bfloat16 g_Kh[(size_t)Bn * Nn * Kd];
__device__ __nv_bfloat16 g_Kl[(size_t)Bn * Nn * Kd];
// V fp16 packed as av B-fragments: per [b][mt 0..63]: [kb 0..3][vj 0..63][lane][2] u32
__device__ uint32_t g_Vh[(size_t)Bn * 64 * 16384];
// P fp16 packed as av A-fragments: per [b][nt 0..31][mt 0..63]:
//   [i_blk 0..7][kb 0..3][lane 0..31][4] u32   (4096 u32 = 16KB per tile)
__device__ uint32_t g_Pf[(size_t)Bn * 32 * 64 * 4096];
__device__ float g_L [(size_t)Bn * Nn];        // row sums of shifted exps
__device__ float g_scl[Vd];
__device__ float g_shf[Vd];

// ===========================================================================
// Helpers (portable ISA: sm_80-class mma.sync + cp.async only)
// ===========================================================================
__device__ __forceinline__ uint32_t smem_u32(const void* p) {
    uint32_t a;
    asm("{ .reg .u64 t; cvta.to.shared.u64 t, %1; cvt.u32.u64 %0, t; }" : "=r"(a) : "l"(p));
    return a;
}
__device__ __forceinline__ void cp_async16(uint32_t saddr, const void* gaddr) {
    asm volatile("cp.async.ca.shared.global [%0], [%1], 16;"
                 :: "r"(saddr), "l"(gaddr) : "memory");
}
__device__ __forceinline__ void cp_commit() {
    asm volatile("cp.async.commit_group;" ::: "memory");
}
__device__ __forceinline__ void cp_wait1() {
    asm volatile("cp.async.wait_group 1;" ::: "memory");
}
__device__ __forceinline__ void cp_wait0() {
    asm volatile("cp.async.wait_group 0;" ::: "memory");
}
__device__ __forceinline__ void mma_bf16(float* d, const uint32_t* a, const uint32_t* b) {
    asm volatile(
        "mma.sync.aligned.m16n8k16.row.col.f32.bf16.bf16.f32 "
        "{%0,%1,%2,%3}, {%4,%5,%6,%7}, {%8,%9}, {%0,%1,%2,%3};"
        : "+f"(d[0]), "+f"(d[1]), "+f"(d[2]), "+f"(d[3])
        : "r"(a[0]), "r"(a[1]), "r"(a[2]), "r"(a[3]), "r"(b[0]), "r"(b[1]));
}
__device__ __forceinline__ void mma_f16(float* d, const uint32_t* a, const uint32_t* b) {
    asm volatile(
        "mma.sync.aligned.m16n8k16.row.col.f32.f16.f16.f32 "
        "{%0,%1,%2,%3}, {%4,%5,%6,%7}, {%8,%9}, {%0,%1,%2,%3};"
        : "+f"(d[0]), "+f"(d[1]), "+f"(d[2]), "+f"(d[3])
        : "r"(a[0]), "r"(a[1]), "r"(a[2]), "r"(a[3]), "r"(b[0]), "r"(b[1]));
}
__device__ __forceinline__ uint32_t lds_u32(const char* p) { return *(const uint32_t*)p; }
__device__ __forceinline__ uint32_t bfcat(__nv_bfloat16 lo, __nv_bfloat16 hi) {
    __nv_bfloat162 t; t.x = lo; t.y = hi;
    return *(uint32_t*)&t;
}
__device__ __forceinline__ uint32_t hfcat(__half lo, __half hi) {
    __half2 t; t.x = lo; t.y = hi;
    return *(uint32_t*)&t;
}

// ===========================================================================
// BN scale/shift precompute
// ===========================================================================
__global__ void prep_kernel(const float* __restrict__ gamma, const float* __restrict__ beta,
                            const float* __restrict__ mean,  const float* __restrict__ var) {
    int i = threadIdx.x;
    if (i < Vd) {
        float s = gamma[i] * rsqrtf(var[i] + 1e-5f);
        g_scl[i] = s;
        g_shf[i] = beta[i] - mean[i] * s;
    }
}

// ===========================================================================
// W split: [Wq;Wk] -> bf16 hi/lo
// ===========================================================================
__global__ __launch_bounds__(256) void wsplit_kernel(const float* __restrict__ Wq,
                                                     const float* __restrict__ Wk) {
    int id = blockIdx.x * 256 + threadIdx.x;
    int o = id >> 9, cc = id & 511;
    float v = (o < 64) ? Wq[o * Cc + cc] : Wk[(o - 64) * Cc + cc];
    __nv_bfloat16 h = __float2bfloat16(v);
    g_Wh[id] = h;
    g_Wl[id] = __float2bfloat16(v - __bfloat162float(h));
}

// ===========================================================================
// Wv -> fp16
// ===========================================================================
__global__ __launch_bounds__(256) void wvhalf_kernel(const float* __restrict__ Wv) {
    int id = blockIdx.x * 256 + threadIdx.x;     // 512*512
    g_Wvf[id] = __float2half(Wv[id]);
}

// ===========================================================================
// X split + transpose: x[b][c][n] fp32 -> [b][n][c]: bf16 hi/lo + fp16
// ===========================================================================
__global__ __launch_bounds__(256) void xsplit_kernel(const float* __restrict__ x) {
    __shared__ float t[32][33];
    const int b = blockIdx.z, n0 = blockIdx.x * 32, c0 = blockIdx.y * 32;
    const int tx = threadIdx.x & 31, ty = threadIdx.x >> 5;
    #pragma unroll
    for (int p = 0; p < 4; p++)
        t[ty + 8 * p][tx] = x[((size_t)b * Cc + c0 + ty + 8 * p) * Nn + n0 + tx];
    __syncthreads();
    #pragma unroll
    for (int p = 0; p < 4; p++) {
        float v = t[tx][ty + 8 * p];
        __nv_bfloat16 h = __float2bfloat16(v);
        __nv_bfloat16 l = __float2bfloat16(v - __bfloat162float(h));
        size_t idx = ((size_t)b * Nn + n0 + ty + 8 * p) * Cc + c0 + tx;
        g_Xh[idx] = h;
        g_Xl[idx] = l;
        g_Xf[idx] = __float2half(v);
    }
}

// ===========================================================================
// Q+K projection on mma.sync bf16 (3-term split)   (unchanged)
// ===========================================================================
static constexpr int QK_XH0 = 0,     QK_XH1 = 5120;
static constexpr int QK_XL0 = 10240, QK_XL1 = 15360;
static constexpr int QK_WH0 = 20480, QK_WH1 = 30720;
static constexpr int QK_WL0 = 40960, QK_WL1 = 51200;
static constexpr int QK_BYTES = 61440;

__device__ __forceinline__ void qk_stage(uint32_t sbase, int buf, int b, int n0, int kc) {
    const int t = threadIdx.x;
    const uint32_t xh = sbase + (buf ? QK_XH1 : QK_XH0);
    const uint32_t xl = sbase + (buf ? QK_XL1 : QK_XL0);
    const uint32_t wh = sbase + (buf ? QK_WH1 : QK_WH0);
    const uint32_t wl = sbase + (buf ? QK_WL1 : QK_WL0);
    {
        int r = t >> 2, c4 = t & 3;
        size_t src = ((size_t)b * Nn + n0 + r) * Cc + kc * 32 + c4 * 8;
        cp_async16(xh + r * 80 + c4 * 16, g_Xh + src);
        cp_async16(xl + r * 80 + c4 * 16, g_Xl + src);
    }
    #pragma unroll
    for (int p = 0; p < 2; p++) {
        int id = t + 256 * p, r = id >> 2, c4 = id & 3;
        size_t src = (size_t)r * Cc + kc * 32 + c4 * 8;
        cp_async16(wh + r * 80 + c4 * 16, g_Wh + src);
        cp_async16(wl + r * 80 + c4 * 16, g_Wl + src);
    }
}

__global__ __launch_bounds__(256) void qk_mma_kernel(const float* __restrict__ bq,
                                                     const float* __restrict__ bk) {
    extern __shared__ char smc[];
    const uint32_t sbase = smem_u32(smc);
    const int tid = threadIdx.x;
    const int wid = tid >> 5, lane = tid & 31;
    const int g = lane >> 2, c = lane & 3;
    const int wn = wid & 1, wo = wid >> 1;
    const int b  = blockIdx.z;
    const int n0 = blockIdx.x * 64;

    float acc[2][4][4] = {};

    qk_stage(sbase, 0, b, n0, 0);
    cp_commit();

    for (int kc = 0; kc < 16; kc++) {
        const int cur = kc & 1;
        if (kc + 1 < 16) {
            qk_stage(sbase, cur ^ 1, b, n0, kc + 1);
            cp_commit();
            cp_wait1();
        } else {
            cp_wait0();
        }
        __syncthreads();

        const char* XH = smc + (cur ? QK_XH1 : QK_XH0);
        const char* XL = smc + (cur ? QK_XL1 : QK_XL0);
        const char* WH = smc + (cur ? QK_WH1 : QK_WH0);
        const char* WL = smc + (cur ? QK_WL1 : QK_WL0);

        #pragma unroll
        for (int ks = 0; ks < 2; ks++) {
            uint32_t ah[2][4], al[2][4];
            #pragma unroll
            for (int i = 0; i < 2; i++) {
                const int off = (wn * 32 + i * 16 + g) * 80 + ks * 32 + c * 4;
                ah[i][0] = lds_u32(XH + off);
                ah[i][1] = lds_u32(XH + off + 8 * 80);
                ah[i][2] = lds_u32(XH + off + 16);
                ah[i][3] = lds_u32(XH + off + 8 * 80 + 16);
                al[i][0] = lds_u32(XL + off);
                al[i][1] = lds_u32(XL + off + 8 * 80);
                al[i][2] = lds_u32(XL + off + 16);
                al[i][3] = lds_u32(XL + off + 8 * 80 + 16);
            }
            uint32_t bh[4][2], bl[4][2];
            #pragma unroll
            for (int j = 0; j < 4; j++) {
                const int off = (wo * 32 + j * 8 + g) * 80 + ks * 32 + c * 4;
                bh[j][0] = lds_u32(WH + off);
                bh[j][1] = lds_u32(WH + off + 16);
                bl[j][0] = lds_u32(WL + off);
                bl[j][1] = lds_u32(WL + off + 16);
            }
            #pragma unroll
            for (int i = 0; i < 2; i++)
                #pragma unroll
                for (int j = 0; j < 4; j++) {
                    mma_bf16(acc[i][j], ah[i], bh[j]);
                    mma_bf16(acc[i][j], ah[i], bl[j]);
                    mma_bf16(acc[i][j], al[i], bh[j]);
                }
        }
        __syncthreads();
    }

    const int which = wo >> 1;
    __nv_bfloat16* dh = which ? g_Kh : g_Qh;
    __nv_bfloat16* dl = which ? g_Kl : g_Ql;
    const float* bias = which ? bk : bq;
    #pragma unroll
    for (int i = 0; i < 2; i++) {
        const int n_lo = n0 + wn * 32 + i * 16 + g;
        #pragma unroll
        for (int j = 0; j < 4; j++) {
            const int o = (wo * 32 + j * 8 + 2 * c) & 63;
            const float b0 = bias[o], b1 = bias[o + 1];
            float v00 = acc[i][j][0] + b0, v01 = acc[i][j][1] + b1;
            float v10 = acc[i][j][2] + b0, v11 = acc[i][j][3] + b1;
            __nv_bfloat16 h00 = __float2bfloat16(v00), h01 = __float2bfloat16(v01);
            __nv_bfloat16 h10 = __float2bfloat16(v10), h11 = __float2bfloat16(v11);
            __nv_bfloat16 l00 = __float2bfloat16(v00 - __bfloat162float(h00));
            __nv_bfloat16 l01 = __float2bfloat16(v01 - __bfloat162float(h01));
            __nv_bfloat16 l10 = __float2bfloat16(v10 - __bfloat162float(h10));
            __nv_bfloat16 l11 = __float2bfloat16(v11 - __bfloat162float(h11));
            size_t r0 = ((size_t)b * Nn + n_lo) * Kd + o;
            size_t r1 = ((size_t)b * Nn + n_lo + 8) * Kd + o;
            *(uint32_t*)&dh[r0] = bfcat(h00, h01);
            *(uint32_t*)&dh[r1] = bfcat(h10, h11);
            *(uint32_t*)&dl[r0] = bfcat(l00, l01);
            *(uint32_t*)&dl[r1] = bfcat(l10, l11);
        }
    }
}

// ===========================================================================
// V projection on single-pass fp16 mma.sync   (unchanged)
// ===========================================================================
static constexpr int VP_W0 = 0,     VP_W1 = 10240;
static constexpr int VP_X0 = 20480, VP_X1 = 30720;
static constexpr int VP_BYTES = 40960;

__device__ __forceinline__ void vproj_stage(uint32_t sbase, int buf, int b,
                                            int m0, int v0, int kc) {
    const int t = threadIdx.x;
    const uint32_t sW = sbase + (buf ? VP_W1 : VP_W0);
    const uint32_t sX = sbase + (buf ? VP_X1 : VP_X0);
    #pragma unroll
    for (int p = 0; p < 2; p++) {
        int id = t + 256 * p, r = id >> 2, c4 = id & 3;
        cp_async16(sW + r * 80 + c4 * 16,
                   g_Wvf + (size_t)(v0 + r) * Cc + kc * 32 + c4 * 8);
    }
    #pragma unroll
    for (int p = 0; p < 2; p++) {
        int id = t + 256 * p, r = id >> 2, c4 = id & 3;
        cp_async16(sX + r * 80 + c4 * 16,
                   g_Xf + ((size_t)b * Nn + m0 + r) * Cc + kc * 32 + c4 * 8);
    }
}

__global__ __launch_bounds__(256) void vproj_mma_kernel() {
    extern __shared__ char smc[];
    const uint32_t sbase = smem_u32(smc);
    const int tid = threadIdx.x;
    const int wid = tid >> 5, lane = tid & 31;
    const int g = lane >> 2, c = lane & 3;
    const int wn = wid & 1, wv = wid >> 1;
    const int b  = blockIdx.z;
    const int m0 = blockIdx.y * 128;
    const int v0 = blockIdx.x * 128;

    float acc[4][4][4] = {};

    vproj_stage(sbase, 0, b, m0, v0, 0);
    cp_commit();

    for (int kc = 0; kc < Cc / 32; kc++) {
        const int cur = kc & 1;
        if (kc + 1 < Cc / 32) {
            vproj_stage(sbase, cur ^ 1, b, m0, v0, kc + 1);
            cp_commit();
            cp_wait1();
        } else {
            cp_wait0();
        }
        __syncthreads();

        const char* Ws = smc + (cur ? VP_W1 : VP_W0);
        const char* Xs = smc + (cur ? VP_X1 : VP_X0);

        #pragma unroll
        for (int ks = 0; ks < 2; ks++) {
            uint32_t af[4][4];
            #pragma unroll
            for (int i = 0; i < 4; i++) {
                const int off = (wn * 64 + i * 16 + g) * 80 + ks * 32 + c * 4;
                af[i][0] = lds_u32(Ws + off);
                af[i][1] = lds_u32(Ws + off + 8 * 80);
                af[i][2] = lds_u32(Ws + off + 16);
                af[i][3] = lds_u32(Ws + off + 8 * 80 + 16);
            }
            uint32_t bf[4][2];
            #pragma unroll
            for (int j = 0; j < 4; j++) {
                const int off = (wv * 32 + j * 8 + g) * 80 + ks * 32 + c * 4;
                bf[j][0] = lds_u32(Xs + off);
                bf[j][1] = lds_u32(Xs + off + 16);
            }
            #pragma unroll
            for (int i = 0; i < 4; i++)
                #pragma unroll
                for (int j = 0; j < 4; j++)
                    mma_f16(acc[i][j], af[i], bf[j]);
        }
        __syncthreads();
    }

    const int mt = blockIdx.y * 2 + (wv >> 1);
    uint32_t* base = g_Vh + ((size_t)b * 64 + mt) * 16384;
    #pragma unroll
    for (int i = 0; i < 4; i++) {
        const int vg = v0 + wn * 64 + i * 16 + g;
        const float sg = g_scl[vg],     hg = g_shf[vg];
        const float s8 = g_scl[vg + 8], h8 = g_shf[vg + 8];
        const int vj = vg >> 3;
        #pragma unroll
        for (int j = 0; j < 4; j++) {
            const int kb = ((wv * 32 + j * 8) >> 4) & 3;
            const int lohi = j & 1;
            __half a0 = __float2half(fmaxf(fmaf(acc[i][j][0], sg, hg), 0.f));
            __half a1 = __float2half(fmaxf(fmaf(acc[i][j][1], sg, hg), 0.f));
            __half a2 = __float2half(fmaxf(fmaf(acc[i][j][2], s8, h8), 0.f));
            __half a3 = __float2half(fmaxf(fmaf(acc[i][j][3], s8, h8), 0.f));
            base[(size_t)kb * 4096 + (size_t)vj * 64 + lane * 2 + lohi]       = hfcat(a0, a1);
            base[(size_t)kb * 4096 + (size_t)(vj + 1) * 64 + lane * 2 + lohi] = hfcat(a2, a3);
        }
    }
}

// ===========================================================================
// Energy, FUSED max pass (phase 1: hi-only QK^T -> exact row max in regs) +
// 3-term bf16 energy (phase 2: exp(l - M) -> fp16 packed A-frags + g_L).
// grid (Nn/64, Bn), block 256, warps 2(n) x 4(m), warp 32x16.
// ===========================================================================
static constexpr int E_QH  = 0;
static constexpr int E_QL  = 9216;
static constexpr int E_KH0 = 18432;
static constexpr int E_KH1 = 27648;
static constexpr int E_KL0 = 36864;
static constexpr int E_KL1 = 46080;
static constexpr int E_BYTES = 55296;

__global__ __launch_bounds__(256) void energy_mma_kernel() {
    extern __shared__ char smc[];
    __shared__ float sR[4][64];
    const uint32_t sbase = smem_u32(smc);
    const int tid = threadIdx.x;
    const int wid = tid >> 5, lane = tid & 31;
    const int g = lane >> 2, c = lane & 3;
    const int wn = wid & 1, wv = wid >> 1;
    const int b  = blockIdx.y;
    const int n0 = blockIdx.x * 64;
    const int nt = blockIdx.x >> 1;
    const int half = blockIdx.x & 1;

    const size_t qoff = ((size_t)b * Nn + n0) * Kd;
    const size_t koff = (size_t)b * Nn * Kd;

    // ---- Stage Q (hi+lo), resident for both phases ----
    #pragma unroll
    for (int p = 0; p < 2; p++) {
        int id = tid + 256 * p, r = id >> 3, c8 = id & 7;
        cp_async16(sbase + E_QH + r * 144 + c8 * 16, g_Qh + qoff + (size_t)r * Kd + c8 * 8);
        cp_async16(sbase + E_QL + r * 144 + c8 * 16, g_Ql + qoff + (size_t)r * Kd + c8 * 8);
    }
    // K-hi chunk 0 for phase 1
    {
        int r = tid >> 2, c8 = (tid & 3) * 2;
        cp_async16(sbase + E_KH0 + r * 144 + c8 * 16,       g_Kh + koff + (size_t)r * Kd + c8 * 8);
        cp_async16(sbase + E_KH0 + r * 144 + (c8 + 1) * 16, g_Kh + koff + (size_t)r * Kd + (c8 + 1) * 8);
    }
    cp_commit();

    // =============== Phase 1: exact row max (hi-only) ===============
    float mx[2][2] = { { -1e30f, -1e30f }, { -1e30f, -1e30f } };

    for (int mc = 0; mc < 64; mc++) {
        const int cur = mc & 1;
        if (mc + 1 < 64) {
            const uint32_t kh = sbase + ((mc + 1) & 1 ? E_KH1 : E_KH0);
            int r = tid >> 2, c8 = (tid & 3) * 2;
            const size_t rowbase = koff + (size_t)((mc + 1) * 64 + r) * Kd;
            cp_async16(kh + r * 144 + c8 * 16,       g_Kh + rowbase + c8 * 8);
            cp_async16(kh + r * 144 + (c8 + 1) * 16, g_Kh + rowbase + (c8 + 1) * 8);
            cp_commit();
            cp_wait1();
        } else {
            cp_wait0();
        }
        __syncthreads();

        const char* QH = smc + E_QH;
        const char* KH = smc + (cur ? E_KH1 : E_KH0);

        float acc[2][2][4] = {};
        #pragma unroll
        for (int ks = 0; ks < 4; ks++) {
            uint32_t ah[2][4];
            #pragma unroll
            for (int i = 0; i < 2; i++) {
                const int off = (wn * 32 + i * 16 + g) * 144 + ks * 32 + c * 4;
                ah[i][0] = lds_u32(QH + off);
                ah[i][1] = lds_u32(QH + off + 8 * 144);
                ah[i][2] = lds_u32(QH + off + 16);
                ah[i][3] = lds_u32(QH + off + 8 * 144 + 16);
            }
            uint32_t bh[2][2];
            #pragma unroll
            for (int j = 0; j < 2; j++) {
                const int off = (wv * 16 + j * 8 + g) * 144 + ks * 32 + c * 4;
                bh[j][0] = lds_u32(KH + off);
                bh[j][1] = lds_u32(KH + off + 16);
            }
            #pragma unroll
            for (int i = 0; i < 2; i++)
                #pragma unroll
                for (int j = 0; j < 2; j++)
                    mma_bf16(acc[i][j], ah[i], bh[j]);
        }
        __syncthreads();

        #pragma unroll
        for (int i = 0; i < 2; i++)
            #pragma unroll
            for (int j = 0; j < 2; j++) {
                mx[i][0] = fmaxf(mx[i][0], fmaxf(acc[i][j][0], acc[i][j][1]));
                mx[i][1] = fmaxf(mx[i][1], fmaxf(acc[i][j][2], acc[i][j][3]));
            }
    }

    // Block-reduce maxes: over c lanes, then over the 4 wv warps via sR.
    #pragma unroll
    for (int i = 0; i < 2; i++)
        #pragma unroll
        for (int r = 0; r < 2; r++) {
            float v = mx[i][r];
            v = fmaxf(v, __shfl_xor_sync(0xffffffffu, v, 1));
            v = fmaxf(v, __shfl_xor_sync(0xffffffffu, v, 2));
            mx[i][r] = v;
        }
    if (c == 0) {
        #pragma unroll
        for (int i = 0; i < 2; i++) {
            sR[wv][wn * 32 + i * 16 + g]     = mx[i][0];
            sR[wv][wn * 32 + i * 16 + g + 8] = mx[i][1];
        }
    }
    __syncthreads();

    float Mv[2][2];
    #pragma unroll
    for (int i = 0; i < 2; i++) {
        const int r0 = wn * 32 + i * 16 + g;
        Mv[i][0] = fmaxf(fmaxf(sR[0][r0],     sR[1][r0]),     fmaxf(sR[2][r0],     sR[3][r0]));
        Mv[i][1] = fmaxf(fmaxf(sR[0][r0 + 8], sR[1][r0 + 8]), fmaxf(sR[2][r0 + 8], sR[3][r0 + 8]));
    }
    __syncthreads();   // sR reads done before phase-2 reuse

    // =============== Phase 2: full 3-term energy + exp ===============
    #pragma unroll
    for (int p = 0; p < 2; p++) {
        int id = tid + 256 * p, r = id >> 3, c8 = id & 7;
        cp_async16(sbase + E_KH0 + r * 144 + c8 * 16, g_Kh + koff + (size_t)r * Kd + c8 * 8);
        cp_async16(sbase + E_KL0 + r * 144 + c8 * 16, g_Kl + koff + (size_t)r * Kd + c8 * 8);
    }
    cp_commit();

    float rsum[2][2] = {};

    for (int mc = 0; mc < 64; mc++) {
        const int cur = mc & 1;
        if (mc + 1 < 64) {
            const uint32_t kh = sbase + ((mc + 1) & 1 ? E_KH1 : E_KH0);
            const uint32_t kl = sbase + ((mc + 1) & 1 ? E_KL1 : E_KL0);
            #pragma unroll
            for (int p = 0; p < 2; p++) {
                int id = tid + 256 * p, r = id >> 3, c8 = id & 7;
                cp_async16(kh + r * 144 + c8 * 16,
                           g_Kh + koff + (size_t)((mc + 1) * 64 + r) * Kd + c8 * 8);
                cp_async16(kl + r * 144 + c8 * 16,
                           g_Kl + koff + (size_t)((mc + 1) * 64 + r) * Kd + c8 * 8);
            }
            cp_commit();
            cp_wait1();
        } else {
            cp_wait0();
        }
        __syncthreads();

        const char* QH = smc + E_QH;
        const char* QL = smc + E_QL;
        const char* KH = smc + (cur ? E_KH1 : E_KH0);
        const char* KL = smc + (cur ? E_KL1 : E_KL0);

        float acc[2][2][4] = {};
        #pragma unroll
        for (int ks = 0; ks < 4; ks++) {
            uint32_t ah[2][4], al[2][4];
            #pragma unroll
            for (int i = 0; i < 2; i++) {
                const int off = (wn * 32 + i * 16 + g) * 144 + ks * 32 + c * 4;
                ah[i][0] = lds_u32(QH + off);
                ah[i][1] = lds_u32(QH + off + 8 * 144);
                ah[i][2] = lds_u32(QH + off + 16);
                ah[i][3] = lds_u32(QH + off + 8 * 144 + 16);
                al[i][0] = lds_u32(QL + off);
                al[i][1] = lds_u32(QL + off + 8 * 144);
                al[i][2] = lds_u32(QL + off + 16);
                al[i][3] = lds_u32(QL + off + 8 * 144 + 16);
            }
            uint32_t bh[2][2], bl[2][2];
            #pragma unroll
            for (int j = 0; j < 2; j++) {
                const int off = (wv * 16 + j * 8 + g) * 144 + ks * 32 + c * 4;
                bh[j][0] = lds_u32(KH + off);
                bh[j][1] = lds_u32(KH + off + 16);
                bl[j][0] = lds_u32(KL + off);
                bl[j][1] = lds_u32(KL + off + 16);
            }
            #pragma unroll
            for (int i = 0; i < 2; i++)
                #pragma unroll
                for (int j = 0; j < 2; j++) {
                    mma_bf16(acc[i][j], ah[i], bh[j]);
                    mma_bf16(acc[i][j], ah[i], bl[j]);
                    mma_bf16(acc[i][j], al[i], bh[j]);
                }
        }
        __syncthreads();

        const size_t tile0 = (((size_t)b * 32 + nt) * 64 + mc) * 4096;
        #pragma unroll
        for (int i = 0; i < 2; i++) {
            const int i_blk = half * 4 + wn * 2 + i;
            __half h[2][4];
            #pragma unroll
            for (int j = 0; j < 2; j++) {
                h[j][0] = __float2half(__expf(acc[i][j][0] - Mv[i][0]));
                h[j][1] = __float2half(__expf(acc[i][j][1] - Mv[i][0]));
                h[j][2] = __float2half(__expf(acc[i][j][2] - Mv[i][1]));
                h[j][3] = __float2half(__expf(acc[i][j][3] - Mv[i][1]));
                rsum[i][0] += __half2float(h[j][0]) + __half2float(h[j][1]);
                rsum[i][1] += __half2float(h[j][2]) + __half2float(h[j][3]);
            }
            uint4 w4;
            w4.x = hfcat(h[0][0], h[0][1]);
            w4.y = hfcat(h[0][2], h[0][3]);
            w4.z = hfcat(h[1][0], h[1][1]);
            w4.w = hfcat(h[1][2], h[1][3]);
            *(uint4*)&g_Pf[tile0 + (size_t)((i_blk * 4 + wv) * 128 + lane * 4)] = w4;
        }
    }

    #pragma unroll
    for (int i = 0; i < 2; i++)
        #pragma unroll
        for (int r = 0; r < 2; r++) {
            float v = rsum[i][r];
            v += __shfl_xor_sync(0xffffffffu, v, 1);
            v += __shfl_xor_sync(0xffffffffu, v, 2);
            rsum[i][r] = v;
        }
    if (c == 0) {
        #pragma unroll
        for (int i = 0; i < 2; i++) {
            sR[wv][wn * 32 + i * 16 + g]     = rsum[i][0];
            sR[wv][wn * 32 + i * 16 + g + 8] = rsum[i][1];
        }
    }
    __syncthreads();
    if (tid < 64)
        g_L[(size_t)b * Nn + n0 + tid] = sR[0][tid] + sR[1][tid] + sR[2][tid] + sR[3][tid];
}

// ===========================================================================
// PV GEMM on fp16 m16n8k16, packed fragments, K-chunk 64 (R11 proven form):
//   out[b][v][n] = (1/L[n]) * sum_m P[n][m] V[m][v]
// Block 128(n) x 128(v), warp 64x32 (2x4 warps), 2-stage.
// SMEM u32: A stages @ {0, 4096} (16KB), B @ {8192, 12288} (16KB). 64KB.
// ===========================================================================
static constexpr int AV_BYTES = 65536;

__device__ __forceinline__ void av_stage(uint32_t sbase, int buf,
                                         const uint32_t* gA, const uint32_t* gB,
                                         int v0j, int mt) {
    const int t = threadIdx.x;
    const uint32_t sA = sbase + (buf ? 4096u : 0u) * 4;
    const uint32_t sB = sbase + (8192u + buf * 4096u) * 4;
    const uint32_t* gAt = gA + (size_t)mt * 4096;
    const uint32_t* gBt = gB + (size_t)mt * 16384 + (size_t)v0j * 64;
    #pragma unroll
    for (int p = 0; p < 4; p++) {   // A: linear 1024 x 16B
        int id = t + 256 * p;
        cp_async16(sA + (uint32_t)id * 16, gAt + id * 4);
    }
    #pragma unroll
    for (int p = 0; p < 4; p++) {   // B: 4 kb x 16 vj x 64 u32
        int id = t + 256 * p, kb = id >> 8, rem = id & 255;
        int vjl = rem >> 4, q = rem & 15;
        cp_async16(sB + (uint32_t)(kb * 1024 + vjl * 64 + q * 4) * 4,
                   gBt + (size_t)kb * 4096 + (size_t)vjl * 64 + q * 4);
    }
}

__global__ __launch_bounds__(256, 2) void av_mma_kernel(float* __restrict__ out) {
    extern __shared__ uint32_t smu[];
    const uint32_t sbase = smem_u32(smu);
    const int tid  = threadIdx.x;
    const int wid  = tid >> 5, lane = tid & 31;
    const int g = lane >> 2, c = lane & 3;
    const int wn = wid & 1, wv = wid >> 1;
    const int b  = blockIdx.z;
    const int nt = blockIdx.y;
    const int n0 = nt * 128;
    const int v0 = blockIdx.x * 128;

    const uint32_t* gA = g_Pf + (((size_t)b * 32 + nt) * 64) * 4096;
    const uint32_t* gB = g_Vh + ((size_t)b * 64) * 16384;

    float acc[4][4][4] = {};

    av_stage(sbase, 0, gA, gB, v0 >> 3, 0);
    cp_commit();

    for (int mt = 0; mt < 64; mt++) {
        const int cur = mt & 1;
        if (mt + 1 < 64) {
            av_stage(sbase, cur ^ 1, gA, gB, v0 >> 3, mt + 1);
            cp_commit();
            cp_wait1();
        } else {
            cp_wait0();
        }
        __syncthreads();

        const uint32_t* As = smu + cur * 4096;
        const uint32_t* Bs = smu + 8192 + cur * 4096;

        #pragma unroll
        for (int kb = 0; kb < 4; kb++) {
            uint4 af[4];
            #pragma unroll
            for (int i = 0; i < 4; i++)
                af[i] = *(const uint4*)(As + (wn * 4 + i) * 512 + kb * 128 + lane * 4);
            uint2 bfr[4];
            #pragma unroll
            for (int j = 0; j < 4; j++)
                bfr[j] = *(const uint2*)(Bs + kb * 1024 + (wv * 4 + j) * 64 + lane * 2);
            #pragma unroll
            for (int i = 0; i < 4; i++)
                #pragma unroll
                for (int j = 0; j < 4; j++)
                    mma_f16(acc[i][j], (const uint32_t*)&af[i], (const uint32_t*)&bfr[j]);
        }
        __syncthreads();
    }

    #pragma unroll
    for (int i = 0; i < 4; i++) {
        const int n_lo = n0 + wn * 64 + i * 16 + g;
        const float linv_lo = 1.0f / g_L[(size_t)b * Nn + n_lo];
        const float linv_hi = 1.0f / g_L[(size_t)b * Nn + n_lo + 8];
        #pragma unroll
        for (int j = 0; j < 4; j++) {
            const int v = v0 + wv * 32 + j * 8 + c * 2;
            float* o0p = out + ((size_t)b * Vd + v)     * Nn + n_lo;
            float* o1p = out + ((size_t)b * Vd + v + 1) * Nn + n_lo;
            o0p[0] = acc[i][j][0] * linv_lo;
            o1p[0] = acc[i][j][1] * linv_lo;
            o0p[8] = acc[i][j][2] * linv_hi;
            o1p[8] = acc[i][j][3] * linv_hi;
        }
    }
}

// ===========================================================================
extern "C" void kernel_launch(void* const* d_in, const int* in_sizes, int n_in,
                              void* d_out, int out_size) {
    const float* x     = (const float*)d_in[0];
    const float* Wq    = (const float*)d_in[1];
    const float* bq    = (const float*)d_in[2];
    const float* Wk    = (const float*)d_in[3];
    const float* bk    = (const float*)d_in[4];
    const float* Wv    = (const float*)d_in[5];
    const float* gamma = (const float*)d_in[6];
    const float* beta  = (const float*)d_in[7];
    const float* mean  = (const float*)d_in[8];
    const float* var   = (const float*)d_in[9];
    float* out = (float*)d_out;

    static int smem_set = 0;
    if (!smem_set) {
        cudaFuncSetAttribute(qk_mma_kernel,
                             cudaFuncAttributeMaxDynamicSharedMemorySize, QK_BYTES);
        cudaFuncSetAttribute(vproj_mma_kernel,
                             cudaFuncAttributeMaxDynamicSharedMemorySize, VP_BYTES);
        cudaFuncSetAttribute(energy_mma_kernel,
                             cudaFuncAttributeMaxDynamicSharedMemorySize, E_BYTES);
        cudaFuncSetAttribute(av_mma_kernel,
                             cudaFuncAttributeMaxDynamicSharedMemorySize, AV_BYTES);
        smem_set = 1;
    }

    prep_kernel<<<1, 512>>>(gamma, beta, mean, var);
    wsplit_kernel<<<256, 256>>>(Wq, Wk);
    wvhalf_kernel<<<1024, 256>>>(Wv);
    xsplit_kernel<<<dim3(Nn / 32, Cc / 32, Bn), 256>>>(x);

    qk_mma_kernel<<<dim3(Nn / 64, 1, Bn), 256, QK_BYTES>>>(bq, bk);
    vproj_mma_kernel<<<dim3(Vd / 128, Nn / 128, Bn), 256, VP_BYTES>>>();

    energy_mma_kernel<<<dim3(Nn / 64, Bn), 256, E_BYTES>>>();

    av_mma_kernel<<<dim3(Vd / 128, Nn / 128, Bn), 256, AV_BYTES>>>(out);
}

// round 15
// speedup vs baseline: 1.0133x; 1.0095x over previous
#include <cuda_runtime.h>
#include <cuda_bf16.h>
#include <cuda_fp16.h>
#include <cstdint>
#include <cstddef>

static constexpr int Bn = 8;
static constexpr int Cc = 512;
static constexpr int Nn = 4096;   // H*W
static constexpr int Kd = 64;
static constexpr int Vd = 512;

// Scratch (device globals)
__device__ __nv_bfloat16 g_Xh[(size_t)Bn * Nn * Cc];   // x transposed [b][n][c] bf16 hi
__device__ __nv_bfloat16 g_Xl[(size_t)Bn * Nn * Cc];
__device__ __half        g_Xf[(size_t)Bn * Nn * Cc];   // x transposed [b][n][c] fp16
__device__ __nv_bfloat16 g_Wh[128 * Cc];               // [Wq;Wk]
__device__ __nv_bfloat16 g_Wl[128 * Cc];
__device__ __half        g_Wvf[Vd * Cc];               // Wv fp16 [v][c]
__device__ __nv_bfloat16 g_Qh[(size_t)Bn * Nn * Kd];
__device__ __nv_bfloat16 g_Ql[(size_t)Bn * Nn * Kd];
__device__ __nv_bfloat16 g_Kh[(size_t)Bn * Nn * Kd];
__device__ __nv_bfloat16 g_Kl[(size_t)Bn * Nn * Kd];
// V fp16 packed as av B-fragments: per [b][mt 0..63]: [kb 0..3][vj 0..63][lane][2] u32
__device__ uint32_t g_Vh[(size_t)Bn * 64 * 16384];
// P fp16 packed as av A-fragments: per [b][nt 0..31][mt 0..63]:
//   [i_blk 0..7][kb 0..3][lane 0..31][4] u32   (4096 u32 = 16KB per tile)
__device__ uint32_t g_Pf[(size_t)Bn * 32 * 64 * 4096];
__device__ float g_L [(size_t)Bn * Nn];        // row sums of shifted exps
__device__ float g_scl[Vd];
__device__ float g_shf[Vd];

// ===========================================================================
// Helpers (portable ISA: sm_80-class mma.sync + cp.async only)
// ===========================================================================
__device__ __forceinline__ uint32_t smem_u32(const void* p) {
    uint32_t a;
    asm("{ .reg .u64 t; cvta.to.shared.u64 t, %1; cvt.u32.u64 %0, t; }" : "=r"(a) : "l"(p));
    return a;
}
__device__ __forceinline__ void cp_async16(uint32_t saddr, const void* gaddr) {
    asm volatile("cp.async.ca.shared.global [%0], [%1], 16;"
                 :: "r"(saddr), "l"(gaddr) : "memory");
}
__device__ __forceinline__ void cp_commit() {
    asm volatile("cp.async.commit_group;" ::: "memory");
}
__device__ __forceinline__ void cp_wait1() {
    asm volatile("cp.async.wait_group 1;" ::: "memory");
}
__device__ __forceinline__ void cp_wait0() {
    asm volatile("cp.async.wait_group 0;" ::: "memory");
}
__device__ __forceinline__ void mma_bf16(float* d, const uint32_t* a, const uint32_t* b) {
    asm volatile(
        "mma.sync.aligned.m16n8k16.row.col.f32.bf16.bf16.f32 "
        "{%0,%1,%2,%3}, {%4,%5,%6,%7}, {%8,%9}, {%0,%1,%2,%3};"
        : "+f"(d[0]), "+f"(d[1]), "+f"(d[2]), "+f"(d[3])
        : "r"(a[0]), "r"(a[1]), "r"(a[2]), "r"(a[3]), "r"(b[0]), "r"(b[1]));
}
__device__ __forceinline__ void mma_f16(float* d, const uint32_t* a, const uint32_t* b) {
    asm volatile(
        "mma.sync.aligned.m16n8k16.row.col.f32.f16.f16.f32 "
        "{%0,%1,%2,%3}, {%4,%5,%6,%7}, {%8,%9}, {%0,%1,%2,%3};"
        : "+f"(d[0]), "+f"(d[1]), "+f"(d[2]), "+f"(d[3])
        : "r"(a[0]), "r"(a[1]), "r"(a[2]), "r"(a[3]), "r"(b[0]), "r"(b[1]));
}
__device__ __forceinline__ uint32_t lds_u32(const char* p) { return *(const uint32_t*)p; }
__device__ __forceinline__ uint32_t bfcat(__nv_bfloat16 lo, __nv_bfloat16 hi) {
    __nv_bfloat162 t; t.x = lo; t.y = hi;
    return *(uint32_t*)&t;
}
__device__ __forceinline__ uint32_t hfcat(__half lo, __half hi) {
    __half2 t; t.x = lo; t.y = hi;
    return *(uint32_t*)&t;
}

// ===========================================================================
// BN scale/shift precompute
// ===========================================================================
__global__ void prep_kernel(const float* __restrict__ gamma, const float* __restrict__ beta,
                            const float* __restrict__ mean,  const float* __restrict__ var) {
    int i = threadIdx.x;
    if (i < Vd) {
        float s = gamma[i] * rsqrtf(var[i] + 1e-5f);
        g_scl[i] = s;
        g_shf[i] = beta[i] - mean[i] * s;
    }
}

// ===========================================================================
// W split: [Wq;Wk] -> bf16 hi/lo
// ===========================================================================
__global__ __launch_bounds__(256) void wsplit_kernel(const float* __restrict__ Wq,
                                                     const float* __restrict__ Wk) {
    int id = blockIdx.x * 256 + threadIdx.x;
    int o = id >> 9, cc = id & 511;
    float v = (o < 64) ? Wq[o * Cc + cc] : Wk[(o - 64) * Cc + cc];
    __nv_bfloat16 h = __float2bfloat16(v);
    g_Wh[id] = h;
    g_Wl[id] = __float2bfloat16(v - __bfloat162float(h));
}

// ===========================================================================
// Wv -> fp16
// ===========================================================================
__global__ __launch_bounds__(256) void wvhalf_kernel(const float* __restrict__ Wv) {
    int id = blockIdx.x * 256 + threadIdx.x;     // 512*512
    g_Wvf[id] = __float2half(Wv[id]);
}

// ===========================================================================
// X split + transpose: x[b][c][n] fp32 -> [b][n][c]: bf16 hi/lo + fp16
// ===========================================================================
__global__ __launch_bounds__(256) void xsplit_kernel(const float* __restrict__ x) {
    __shared__ float t[32][33];
    const int b = blockIdx.z, n0 = blockIdx.x * 32, c0 = blockIdx.y * 32;
    const int tx = threadIdx.x & 31, ty = threadIdx.x >> 5;
    #pragma unroll
    for (int p = 0; p < 4; p++)
        t[ty + 8 * p][tx] = x[((size_t)b * Cc + c0 + ty + 8 * p) * Nn + n0 + tx];
    __syncthreads();
    #pragma unroll
    for (int p = 0; p < 4; p++) {
        float v = t[tx][ty + 8 * p];
        __nv_bfloat16 h = __float2bfloat16(v);
        __nv_bfloat16 l = __float2bfloat16(v - __bfloat162float(h));
        size_t idx = ((size_t)b * Nn + n0 + ty + 8 * p) * Cc + c0 + tx;
        g_Xh[idx] = h;
        g_Xl[idx] = l;
        g_Xf[idx] = __float2half(v);
    }
}

// ===========================================================================
// Q+K projection on mma.sync bf16 (3-term split)   (unchanged)
// ===========================================================================
static constexpr int QK_XH0 = 0,     QK_XH1 = 5120;
static constexpr int QK_XL0 = 10240, QK_XL1 = 15360;
static constexpr int QK_WH0 = 20480, QK_WH1 = 30720;
static constexpr int QK_WL0 = 40960, QK_WL1 = 51200;
static constexpr int QK_BYTES = 61440;

__device__ __forceinline__ void qk_stage(uint32_t sbase, int buf, int b, int n0, int kc) {
    const int t = threadIdx.x;
    const uint32_t xh = sbase + (buf ? QK_XH1 : QK_XH0);
    const uint32_t xl = sbase + (buf ? QK_XL1 : QK_XL0);
    const uint32_t wh = sbase + (buf ? QK_WH1 : QK_WH0);
    const uint32_t wl = sbase + (buf ? QK_WL1 : QK_WL0);
    {
        int r = t >> 2, c4 = t & 3;
        size_t src = ((size_t)b * Nn + n0 + r) * Cc + kc * 32 + c4 * 8;
        cp_async16(xh + r * 80 + c4 * 16, g_Xh + src);
        cp_async16(xl + r * 80 + c4 * 16, g_Xl + src);
    }
    #pragma unroll
    for (int p = 0; p < 2; p++) {
        int id = t + 256 * p, r = id >> 2, c4 = id & 3;
        size_t src = (size_t)r * Cc + kc * 32 + c4 * 8;
        cp_async16(wh + r * 80 + c4 * 16, g_Wh + src);
        cp_async16(wl + r * 80 + c4 * 16, g_Wl + src);
    }
}

__global__ __launch_bounds__(256) void qk_mma_kernel(const float* __restrict__ bq,
                                                     const float* __restrict__ bk) {
    extern __shared__ char smc[];
    const uint32_t sbase = smem_u32(smc);
    const int tid = threadIdx.x;
    const int wid = tid >> 5, lane = tid & 31;
    const int g = lane >> 2, c = lane & 3;
    const int wn = wid & 1, wo = wid >> 1;
    const int b  = blockIdx.z;
    const int n0 = blockIdx.x * 64;

    float acc[2][4][4] = {};

    qk_stage(sbase, 0, b, n0, 0);
    cp_commit();

    for (int kc = 0; kc < 16; kc++) {
        const int cur = kc & 1;
        if (kc + 1 < 16) {
            qk_stage(sbase, cur ^ 1, b, n0, kc + 1);
            cp_commit();
            cp_wait1();
        } else {
            cp_wait0();
        }
        __syncthreads();

        const char* XH = smc + (cur ? QK_XH1 : QK_XH0);
        const char* XL = smc + (cur ? QK_XL1 : QK_XL0);
        const char* WH = smc + (cur ? QK_WH1 : QK_WH0);
        const char* WL = smc + (cur ? QK_WL1 : QK_WL0);

        #pragma unroll
        for (int ks = 0; ks < 2; ks++) {
            uint32_t ah[2][4], al[2][4];
            #pragma unroll
            for (int i = 0; i < 2; i++) {
                const int off = (wn * 32 + i * 16 + g) * 80 + ks * 32 + c * 4;
                ah[i][0] = lds_u32(XH + off);
                ah[i][1] = lds_u32(XH + off + 8 * 80);
                ah[i][2] = lds_u32(XH + off + 16);
                ah[i][3] = lds_u32(XH + off + 8 * 80 + 16);
                al[i][0] = lds_u32(XL + off);
                al[i][1] = lds_u32(XL + off + 8 * 80);
                al[i][2] = lds_u32(XL + off + 16);
                al[i][3] = lds_u32(XL + off + 8 * 80 + 16);
            }
            uint32_t bh[4][2], bl[4][2];
            #pragma unroll
            for (int j = 0; j < 4; j++) {
                const int off = (wo * 32 + j * 8 + g) * 80 + ks * 32 + c * 4;
                bh[j][0] = lds_u32(WH + off);
                bh[j][1] = lds_u32(WH + off + 16);
                bl[j][0] = lds_u32(WL + off);
                bl[j][1] = lds_u32(WL + off + 16);
            }
            #pragma unroll
            for (int i = 0; i < 2; i++)
                #pragma unroll
                for (int j = 0; j < 4; j++) {
                    mma_bf16(acc[i][j], ah[i], bh[j]);
                    mma_bf16(acc[i][j], ah[i], bl[j]);
                    mma_bf16(acc[i][j], al[i], bh[j]);
                }
        }
        __syncthreads();
    }

    const int which = wo >> 1;
    __nv_bfloat16* dh = which ? g_Kh : g_Qh;
    __nv_bfloat16* dl = which ? g_Kl : g_Ql;
    const float* bias = which ? bk : bq;
    #pragma unroll
    for (int i = 0; i < 2; i++) {
        const int n_lo = n0 + wn * 32 + i * 16 + g;
        #pragma unroll
        for (int j = 0; j < 4; j++) {
            const int o = (wo * 32 + j * 8 + 2 * c) & 63;
            const float b0 = bias[o], b1 = bias[o + 1];
            float v00 = acc[i][j][0] + b0, v01 = acc[i][j][1] + b1;
            float v10 = acc[i][j][2] + b0, v11 = acc[i][j][3] + b1;
            __nv_bfloat16 h00 = __float2bfloat16(v00), h01 = __float2bfloat16(v01);
            __nv_bfloat16 h10 = __float2bfloat16(v10), h11 = __float2bfloat16(v11);
            __nv_bfloat16 l00 = __float2bfloat16(v00 - __bfloat162float(h00));
            __nv_bfloat16 l01 = __float2bfloat16(v01 - __bfloat162float(h01));
            __nv_bfloat16 l10 = __float2bfloat16(v10 - __bfloat162float(h10));
            __nv_bfloat16 l11 = __float2bfloat16(v11 - __bfloat162float(h11));
            size_t r0 = ((size_t)b * Nn + n_lo) * Kd + o;
            size_t r1 = ((size_t)b * Nn + n_lo + 8) * Kd + o;
            *(uint32_t*)&dh[r0] = bfcat(h00, h01);
            *(uint32_t*)&dh[r1] = bfcat(h10, h11);
            *(uint32_t*)&dl[r0] = bfcat(l00, l01);
            *(uint32_t*)&dl[r1] = bfcat(l10, l11);
        }
    }
}

// ===========================================================================
// V projection on single-pass fp16 mma.sync   (unchanged)
// ===========================================================================
static constexpr int VP_W0 = 0,     VP_W1 = 10240;
static constexpr int VP_X0 = 20480, VP_X1 = 30720;
static constexpr int VP_BYTES = 40960;

__device__ __forceinline__ void vproj_stage(uint32_t sbase, int buf, int b,
                                            int m0, int v0, int kc) {
    const int t = threadIdx.x;
    const uint32_t sW = sbase + (buf ? VP_W1 : VP_W0);
    const uint32_t sX = sbase + (buf ? VP_X1 : VP_X0);
    #pragma unroll
    for (int p = 0; p < 2; p++) {
        int id = t + 256 * p, r = id >> 2, c4 = id & 3;
        cp_async16(sW + r * 80 + c4 * 16,
                   g_Wvf + (size_t)(v0 + r) * Cc + kc * 32 + c4 * 8);
    }
    #pragma unroll
    for (int p = 0; p < 2; p++) {
        int id = t + 256 * p, r = id >> 2, c4 = id & 3;
        cp_async16(sX + r * 80 + c4 * 16,
                   g_Xf + ((size_t)b * Nn + m0 + r) * Cc + kc * 32 + c4 * 8);
    }
}

__global__ __launch_bounds__(256) void vproj_mma_kernel() {
    extern __shared__ char smc[];
    const uint32_t sbase = smem_u32(smc);
    const int tid = threadIdx.x;
    const int wid = tid >> 5, lane = tid & 31;
    const int g = lane >> 2, c = lane & 3;
    const int wn = wid & 1, wv = wid >> 1;
    const int b  = blockIdx.z;
    const int m0 = blockIdx.y * 128;
    const int v0 = blockIdx.x * 128;

    float acc[4][4][4] = {};

    vproj_stage(sbase, 0, b, m0, v0, 0);
    cp_commit();

    for (int kc = 0; kc < Cc / 32; kc++) {
        const int cur = kc & 1;
        if (kc + 1 < Cc / 32) {
            vproj_stage(sbase, cur ^ 1, b, m0, v0, kc + 1);
            cp_commit();
            cp_wait1();
        } else {
            cp_wait0();
        }
        __syncthreads();

        const char* Ws = smc + (cur ? VP_W1 : VP_W0);
        const char* Xs = smc + (cur ? VP_X1 : VP_X0);

        #pragma unroll
        for (int ks = 0; ks < 2; ks++) {
            uint32_t af[4][4];
            #pragma unroll
            for (int i = 0; i < 4; i++) {
                const int off = (wn * 64 + i * 16 + g) * 80 + ks * 32 + c * 4;
                af[i][0] = lds_u32(Ws + off);
                af[i][1] = lds_u32(Ws + off + 8 * 80);
                af[i][2] = lds_u32(Ws + off + 16);
                af[i][3] = lds_u32(Ws + off + 8 * 80 + 16);
            }
            uint32_t bf[4][2];
            #pragma unroll
            for (int j = 0; j < 4; j++) {
                const int off = (wv * 32 + j * 8 + g) * 80 + ks * 32 + c * 4;
                bf[j][0] = lds_u32(Xs + off);
                bf[j][1] = lds_u32(Xs + off + 16);
            }
            #pragma unroll
            for (int i = 0; i < 4; i++)
                #pragma unroll
                for (int j = 0; j < 4; j++)
                    mma_f16(acc[i][j], af[i], bf[j]);
        }
        __syncthreads();
    }

    const int mt = blockIdx.y * 2 + (wv >> 1);
    uint32_t* base = g_Vh + ((size_t)b * 64 + mt) * 16384;
    #pragma unroll
    for (int i = 0; i < 4; i++) {
        const int vg = v0 + wn * 64 + i * 16 + g;
        const float sg = g_scl[vg],     hg = g_shf[vg];
        const float s8 = g_scl[vg + 8], h8 = g_shf[vg + 8];
        const int vj = vg >> 3;
        #pragma unroll
        for (int j = 0; j < 4; j++) {
            const int kb = ((wv * 32 + j * 8) >> 4) & 3;
            const int lohi = j & 1;
            __half a0 = __float2half(fmaxf(fmaf(acc[i][j][0], sg, hg), 0.f));
            __half a1 = __float2half(fmaxf(fmaf(acc[i][j][1], sg, hg), 0.f));
            __half a2 = __float2half(fmaxf(fmaf(acc[i][j][2], s8, h8), 0.f));
            __half a3 = __float2half(fmaxf(fmaf(acc[i][j][3], s8, h8), 0.f));
            base[(size_t)kb * 4096 + (size_t)vj * 64 + lane * 2 + lohi]       = hfcat(a0, a1);
            base[(size_t)kb * 4096 + (size_t)(vj + 1) * 64 + lane * 2 + lohi] = hfcat(a2, a3);
        }
    }
}

// ===========================================================================
// Energy, FUSED max pass (phase 1: hi-only QK^T -> exact row max in regs) +
// 3-term bf16 energy (phase 2: exp(l - M) -> fp16 packed A-frags + g_L).
// grid (Nn/64, Bn), block 256, warps 2(n) x 4(m), warp 32x16.  (unchanged)
// ===========================================================================
static constexpr int E_QH  = 0;
static constexpr int E_QL  = 9216;
static constexpr int E_KH0 = 18432;
static constexpr int E_KH1 = 27648;
static constexpr int E_KL0 = 36864;
static constexpr int E_KL1 = 46080;
static constexpr int E_BYTES = 55296;

__global__ __launch_bounds__(256) void energy_mma_kernel() {
    extern __shared__ char smc[];
    __shared__ float sR[4][64];
    const uint32_t sbase = smem_u32(smc);
    const int tid = threadIdx.x;
    const int wid = tid >> 5, lane = tid & 31;
    const int g = lane >> 2, c = lane & 3;
    const int wn = wid & 1, wv = wid >> 1;
    const int b  = blockIdx.y;
    const int n0 = blockIdx.x * 64;
    const int nt = blockIdx.x >> 1;
    const int half = blockIdx.x & 1;

    const size_t qoff = ((size_t)b * Nn + n0) * Kd;
    const size_t koff = (size_t)b * Nn * Kd;

    #pragma unroll
    for (int p = 0; p < 2; p++) {
        int id = tid + 256 * p, r = id >> 3, c8 = id & 7;
        cp_async16(sbase + E_QH + r * 144 + c8 * 16, g_Qh + qoff + (size_t)r * Kd + c8 * 8);
        cp_async16(sbase + E_QL + r * 144 + c8 * 16, g_Ql + qoff + (size_t)r * Kd + c8 * 8);
    }
    {
        int r = tid >> 2, c8 = (tid & 3) * 2;
        cp_async16(sbase + E_KH0 + r * 144 + c8 * 16,       g_Kh + koff + (size_t)r * Kd + c8 * 8);
        cp_async16(sbase + E_KH0 + r * 144 + (c8 + 1) * 16, g_Kh + koff + (size_t)r * Kd + (c8 + 1) * 8);
    }
    cp_commit();

    // =============== Phase 1: exact row max (hi-only) ===============
    float mx[2][2] = { { -1e30f, -1e30f }, { -1e30f, -1e30f } };

    for (int mc = 0; mc < 64; mc++) {
        const int cur = mc & 1;
        if (mc + 1 < 64) {
            const uint32_t kh = sbase + ((mc + 1) & 1 ? E_KH1 : E_KH0);
            int r = tid >> 2, c8 = (tid & 3) * 2;
            const size_t rowbase = koff + (size_t)((mc + 1) * 64 + r) * Kd;
            cp_async16(kh + r * 144 + c8 * 16,       g_Kh + rowbase + c8 * 8);
            cp_async16(kh + r * 144 + (c8 + 1) * 16, g_Kh + rowbase + (c8 + 1) * 8);
            cp_commit();
            cp_wait1();
        } else {
            cp_wait0();
        }
        __syncthreads();

        const char* QH = smc + E_QH;
        const char* KH = smc + (cur ? E_KH1 : E_KH0);

        float acc[2][2][4] = {};
        #pragma unroll
        for (int ks = 0; ks < 4; ks++) {
            uint32_t ah[2][4];
            #pragma unroll
            for (int i = 0; i < 2; i++) {
                const int off = (wn * 32 + i * 16 + g) * 144 + ks * 32 + c * 4;
                ah[i][0] = lds_u32(QH + off);
                ah[i][1] = lds_u32(QH + off + 8 * 144);
                ah[i][2] = lds_u32(QH + off + 16);
                ah[i][3] = lds_u32(QH + off + 8 * 144 + 16);
            }
            uint32_t bh[2][2];
            #pragma unroll
            for (int j = 0; j < 2; j++) {
                const int off = (wv * 16 + j * 8 + g) * 144 + ks * 32 + c * 4;
                bh[j][0] = lds_u32(KH + off);
                bh[j][1] = lds_u32(KH + off + 16);
            }
            #pragma unroll
            for (int i = 0; i < 2; i++)
                #pragma unroll
                for (int j = 0; j < 2; j++)
                    mma_bf16(acc[i][j], ah[i], bh[j]);
        }
        __syncthreads();

        #pragma unroll
        for (int i = 0; i < 2; i++)
            #pragma unroll
            for (int j = 0; j < 2; j++) {
                mx[i][0] = fmaxf(mx[i][0], fmaxf(acc[i][j][0], acc[i][j][1]));
                mx[i][1] = fmaxf(mx[i][1], fmaxf(acc[i][j][2], acc[i][j][3]));
            }
    }

    #pragma unroll
    for (int i = 0; i < 2; i++)
        #pragma unroll
        for (int r = 0; r < 2; r++) {
            float v = mx[i][r];
            v = fmaxf(v, __shfl_xor_sync(0xffffffffu, v, 1));
            v = fmaxf(v, __shfl_xor_sync(0xffffffffu, v, 2));
            mx[i][r] = v;
        }
    if (c == 0) {
        #pragma unroll
        for (int i = 0; i < 2; i++) {
            sR[wv][wn * 32 + i * 16 + g]     = mx[i][0];
            sR[wv][wn * 32 + i * 16 + g + 8] = mx[i][1];
        }
    }
    __syncthreads();

    float Mv[2][2];
    #pragma unroll
    for (int i = 0; i < 2; i++) {
        const int r0 = wn * 32 + i * 16 + g;
        Mv[i][0] = fmaxf(fmaxf(sR[0][r0],     sR[1][r0]),     fmaxf(sR[2][r0],     sR[3][r0]));
        Mv[i][1] = fmaxf(fmaxf(sR[0][r0 + 8], sR[1][r0 + 8]), fmaxf(sR[2][r0 + 8], sR[3][r0 + 8]));
    }
    __syncthreads();

    // =============== Phase 2: full 3-term energy + exp ===============
    #pragma unroll
    for (int p = 0; p < 2; p++) {
        int id = tid + 256 * p, r = id >> 3, c8 = id & 7;
        cp_async16(sbase + E_KH0 + r * 144 + c8 * 16, g_Kh + koff + (size_t)r * Kd + c8 * 8);
        cp_async16(sbase + E_KL0 + r * 144 + c8 * 16, g_Kl + koff + (size_t)r * Kd + c8 * 8);
    }
    cp_commit();

    float rsum[2][2] = {};

    for (int mc = 0; mc < 64; mc++) {
        const int cur = mc & 1;
        if (mc + 1 < 64) {
            const uint32_t kh = sbase + ((mc + 1) & 1 ? E_KH1 : E_KH0);
            const uint32_t kl = sbase + ((mc + 1) & 1 ? E_KL1 : E_KL0);
            #pragma unroll
            for (int p = 0; p < 2; p++) {
                int id = tid + 256 * p, r = id >> 3, c8 = id & 7;
                cp_async16(kh + r * 144 + c8 * 16,
                           g_Kh + koff + (size_t)((mc + 1) * 64 + r) * Kd + c8 * 8);
                cp_async16(kl + r * 144 + c8 * 16,
                           g_Kl + koff + (size_t)((mc + 1) * 64 + r) * Kd + c8 * 8);
            }
            cp_commit();
            cp_wait1();
        } else {
            cp_wait0();
        }
        __syncthreads();

        const char* QH = smc + E_QH;
        const char* QL = smc + E_QL;
        const char* KH = smc + (cur ? E_KH1 : E_KH0);
        const char* KL = smc + (cur ? E_KL1 : E_KL0);

        float acc[2][2][4] = {};
        #pragma unroll
        for (int ks = 0; ks < 4; ks++) {
            uint32_t ah[2][4], al[2][4];
            #pragma unroll
            for (int i = 0; i < 2; i++) {
                const int off = (wn * 32 + i * 16 + g) * 144 + ks * 32 + c * 4;
                ah[i][0] = lds_u32(QH + off);
                ah[i][1] = lds_u32(QH + off + 8 * 144);
                ah[i][2] = lds_u32(QH + off + 16);
                ah[i][3] = lds_u32(QH + off + 8 * 144 + 16);
                al[i][0] = lds_u32(QL + off);
                al[i][1] = lds_u32(QL + off + 8 * 144);
                al[i][2] = lds_u32(QL + off + 16);
                al[i][3] = lds_u32(QL + off + 8 * 144 + 16);
            }
            uint32_t bh[2][2], bl[2][2];
            #pragma unroll
            for (int j = 0; j < 2; j++) {
                const int off = (wv * 16 + j * 8 + g) * 144 + ks * 32 + c * 4;
                bh[j][0] = lds_u32(KH + off);
                bh[j][1] = lds_u32(KH + off + 16);
                bl[j][0] = lds_u32(KL + off);
                bl[j][1] = lds_u32(KL + off + 16);
            }
            #pragma unroll
            for (int i = 0; i < 2; i++)
                #pragma unroll
                for (int j = 0; j < 2; j++) {
                    mma_bf16(acc[i][j], ah[i], bh[j]);
                    mma_bf16(acc[i][j], ah[i], bl[j]);
                    mma_bf16(acc[i][j], al[i], bh[j]);
                }
        }
        __syncthreads();

        const size_t tile0 = (((size_t)b * 32 + nt) * 64 + mc) * 4096;
        #pragma unroll
        for (int i = 0; i < 2; i++) {
            const int i_blk = half * 4 + wn * 2 + i;
            __half h[2][4];
            #pragma unroll
            for (int j = 0; j < 2; j++) {
                h[j][0] = __float2half(__expf(acc[i][j][0] - Mv[i][0]));
                h[j][1] = __float2half(__expf(acc[i][j][1] - Mv[i][0]));
                h[j][2] = __float2half(__expf(acc[i][j][2] - Mv[i][1]));
                h[j][3] = __float2half(__expf(acc[i][j][3] - Mv[i][1]));
                rsum[i][0] += __half2float(h[j][0]) + __half2float(h[j][1]);
                rsum[i][1] += __half2float(h[j][2]) + __half2float(h[j][3]);
            }
            uint4 w4;
            w4.x = hfcat(h[0][0], h[0][1]);
            w4.y = hfcat(h[0][2], h[0][3]);
            w4.z = hfcat(h[1][0], h[1][1]);
            w4.w = hfcat(h[1][2], h[1][3]);
            *(uint4*)&g_Pf[tile0 + (size_t)((i_blk * 4 + wv) * 128 + lane * 4)] = w4;
        }
    }

    #pragma unroll
    for (int i = 0; i < 2; i++)
        #pragma unroll
        for (int r = 0; r < 2; r++) {
            float v = rsum[i][r];
            v += __shfl_xor_sync(0xffffffffu, v, 1);
            v += __shfl_xor_sync(0xffffffffu, v, 2);
            rsum[i][r] = v;
        }
    if (c == 0) {
        #pragma unroll
        for (int i = 0; i < 2; i++) {
            sR[wv][wn * 32 + i * 16 + g]     = rsum[i][0];
            sR[wv][wn * 32 + i * 16 + g + 8] = rsum[i][1];
        }
    }
    __syncthreads();
    if (tid < 64)
        g_L[(size_t)b * Nn + n0 + tid] = sR[0][tid] + sR[1][tid] + sR[2][tid] + sR[3][tid];
}

// ===========================================================================
// PV GEMM on fp16 m16n8k16, packed fragments, K-chunk 64 (unchanged)
// ===========================================================================
static constexpr int AV_BYTES = 65536;

__device__ __forceinline__ void av_stage(uint32_t sbase, int buf,
                                         const uint32_t* gA, const uint32_t* gB,
                                         int v0j, int mt) {
    const int t = threadIdx.x;
    const uint32_t sA = sbase + (buf ? 4096u : 0u) * 4;
    const uint32_t sB = sbase + (8192u + buf * 4096u) * 4;
    const uint32_t* gAt = gA + (size_t)mt * 4096;
    const uint32_t* gBt = gB + (size_t)mt * 16384 + (size_t)v0j * 64;
    #pragma unroll
    for (int p = 0; p < 4; p++) {
        int id = t + 256 * p;
        cp_async16(sA + (uint32_t)id * 16, gAt + id * 4);
    }
    #pragma unroll
    for (int p = 0; p < 4; p++) {
        int id = t + 256 * p, kb = id >> 8, rem = id & 255;
        int vjl = rem >> 4, q = rem & 15;
        cp_async16(sB + (uint32_t)(kb * 1024 + vjl * 64 + q * 4) * 4,
                   gBt + (size_t)kb * 4096 + (size_t)vjl * 64 + q * 4);
    }
}

__global__ __launch_bounds__(256, 2) void av_mma_kernel(float* __restrict__ out) {
    extern __shared__ uint32_t smu[];
    const uint32_t sbase = smem_u32(smu);
    const int tid  = threadIdx.x;
    const int wid  = tid >> 5, lane = tid & 31;
    const int g = lane >> 2, c = lane & 3;
    const int wn = wid & 1, wv = wid >> 1;
    const int b  = blockIdx.z;
    const int nt = blockIdx.y;
    const int n0 = nt * 128;
    const int v0 = blockIdx.x * 128;

    const uint32_t* gA = g_Pf + (((size_t)b * 32 + nt) * 64) * 4096;
    const uint32_t* gB = g_Vh + ((size_t)b * 64) * 16384;

    float acc[4][4][4] = {};

    av_stage(sbase, 0, gA, gB, v0 >> 3, 0);
    cp_commit();

    for (int mt = 0; mt < 64; mt++) {
        const int cur = mt & 1;
        if (mt + 1 < 64) {
            av_stage(sbase, cur ^ 1, gA, gB, v0 >> 3, mt + 1);
            cp_commit();
            cp_wait1();
        } else {
            cp_wait0();
        }
        __syncthreads();

        const uint32_t* As = smu + cur * 4096;
        const uint32_t* Bs = smu + 8192 + cur * 4096;

        #pragma unroll
        for (int kb = 0; kb < 4; kb++) {
            uint4 af[4];
            #pragma unroll
            for (int i = 0; i < 4; i++)
                af[i] = *(const uint4*)(As + (wn * 4 + i) * 512 + kb * 128 + lane * 4);
            uint2 bfr[4];
            #pragma unroll
            for (int j = 0; j < 4; j++)
                bfr[j] = *(const uint2*)(Bs + kb * 1024 + (wv * 4 + j) * 64 + lane * 2);
            #pragma unroll
            for (int i = 0; i < 4; i++)
                #pragma unroll
                for (int j = 0; j < 4; j++)
                    mma_f16(acc[i][j], (const uint32_t*)&af[i], (const uint32_t*)&bfr[j]);
        }
        __syncthreads();
    }

    #pragma unroll
    for (int i = 0; i < 4; i++) {
        const int n_lo = n0 + wn * 64 + i * 16 + g;
        const float linv_lo = 1.0f / g_L[(size_t)b * Nn + n_lo];
        const float linv_hi = 1.0f / g_L[(size_t)b * Nn + n_lo + 8];
        #pragma unroll
        for (int j = 0; j < 4; j++) {
            const int v = v0 + wv * 32 + j * 8 + c * 2;
            float* o0p = out + ((size_t)b * Vd + v)     * Nn + n_lo;
            float* o1p = out + ((size_t)b * Vd + v + 1) * Nn + n_lo;
            o0p[0] = acc[i][j][0] * linv_lo;
            o1p[0] = acc[i][j][1] * linv_lo;
            o0p[8] = acc[i][j][2] * linv_hi;
            o1p[8] = acc[i][j][3] * linv_hi;
        }
    }
}

// ===========================================================================
// Launch: two-stream graph. s0: prep/wsplit/xsplit -> qk -> energy -> (join) av
//         s2: (fork) wvhalf -> (after xsplit) vproj -> join
// ===========================================================================
extern "C" void kernel_launch(void* const* d_in, const int* in_sizes, int n_in,
                              void* d_out, int out_size) {
    const float* x     = (const float*)d_in[0];
    const float* Wq    = (const float*)d_in[1];
    const float* bq    = (const float*)d_in[2];
    const float* Wk    = (const float*)d_in[3];
    const float* bk    = (const float*)d_in[4];
    const float* Wv    = (const float*)d_in[5];
    const float* gamma = (const float*)d_in[6];
    const float* beta  = (const float*)d_in[7];
    const float* mean  = (const float*)d_in[8];
    const float* var   = (const float*)d_in[9];
    float* out = (float*)d_out;

    static cudaStream_t s2 = nullptr;
    static cudaEvent_t ev_fork = nullptr, ev_x = nullptr, ev_join = nullptr;
    static int inited = 0;
    if (!inited) {
        cudaFuncSetAttribute(qk_mma_kernel,
                             cudaFuncAttributeMaxDynamicSharedMemorySize, QK_BYTES);
        cudaFuncSetAttribute(vproj_mma_kernel,
                             cudaFuncAttributeMaxDynamicSharedMemorySize, VP_BYTES);
        cudaFuncSetAttribute(energy_mma_kernel,
                             cudaFuncAttributeMaxDynamicSharedMemorySize, E_BYTES);
        cudaFuncSetAttribute(av_mma_kernel,
                             cudaFuncAttributeMaxDynamicSharedMemorySize, AV_BYTES);
        cudaStreamCreateWithFlags(&s2, cudaStreamNonBlocking);
        cudaEventCreateWithFlags(&ev_fork, cudaEventDisableTiming);
        cudaEventCreateWithFlags(&ev_x,    cudaEventDisableTiming);
        cudaEventCreateWithFlags(&ev_join, cudaEventDisableTiming);
        inited = 1;
    }

    // s0 work
    prep_kernel<<<1, 512>>>(gamma, beta, mean, var);
    cudaEventRecord(ev_fork, 0);                 // fork point for s2
    wsplit_kernel<<<256, 256>>>(Wq, Wk);
    xsplit_kernel<<<dim3(Nn / 32, Cc / 32, Bn), 256>>>(x);
    cudaEventRecord(ev_x, 0);                    // xsplit done (Xf ready)

    // s2 branch: wvhalf (independent), then vproj after xsplit
    cudaStreamWaitEvent(s2, ev_fork, 0);
    wvhalf_kernel<<<1024, 256, 0, s2>>>(Wv);
    cudaStreamWaitEvent(s2, ev_x, 0);
    vproj_mma_kernel<<<dim3(Vd / 128, Nn / 128, Bn), 256, VP_BYTES, s2>>>();
    cudaEventRecord(ev_join, s2);

    // s0 continues: qk -> energy
    qk_mma_kernel<<<dim3(Nn / 64, 1, Bn), 256, QK_BYTES>>>(bq, bk);
    energy_mma_kernel<<<dim3(Nn / 64, Bn), 256, E_BYTES>>>();

    // join and run av
    cudaStreamWaitEvent(0, ev_join, 0);
    av_mma_kernel<<<dim3(Vd / 128, Nn / 128, Bn), 256, AV_BYTES>>>(out);
}

// round 16
// speedup vs baseline: 1.0389x; 1.0253x over previous
#include <cuda_runtime.h>
#include <cuda_bf16.h>
#include <cuda_fp16.h>
#include <cstdint>
#include <cstddef>

static constexpr int Bn = 8;
static constexpr int Cc = 512;
static constexpr int Nn = 4096;   // H*W
static constexpr int Kd = 64;
static constexpr int Vd = 512;

// Scratch (device globals)
__device__ __nv_bfloat16 g_Xh[(size_t)Bn * Nn * Cc];   // x transposed [b][n][c] bf16 hi
__device__ __nv_bfloat16 g_Xl[(size_t)Bn * Nn * Cc];
__device__ __half        g_Xf[(size_t)Bn * Nn * Cc];   // x transposed [b][n][c] fp16
__device__ __nv_bfloat16 g_Wh[128 * Cc];               // [Wq;Wk]
__device__ __nv_bfloat16 g_Wl[128 * Cc];
__device__ __half        g_Wvf[Vd * Cc];               // Wv fp16 [v][c]
__device__ __nv_bfloat16 g_Qh[(size_t)Bn * Nn * Kd];
__device__ __nv_bfloat16 g_Ql[(size_t)Bn * Nn * Kd];
__device__ __nv_bfloat16 g_Kh[(size_t)Bn * Nn * Kd];
__device__ __nv_bfloat16 g_Kl[(size_t)Bn * Nn * Kd];
// V fp16 packed as av B-fragments: per [b][mt 0..63]: [kb 0..3][vj 0..63][lane][2] u32
__device__ uint32_t g_Vh[(size_t)Bn * 64 * 16384];
// P fp16 packed as av A-fragments: per [b][nt 0..31][mt 0..63]:
//   [i_blk 0..7][kb 0..3][lane 0..31][4] u32   (4096 u32 = 16KB per tile)
__device__ uint32_t g_Pf[(size_t)Bn * 32 * 64 * 4096];
__device__ float g_L [(size_t)Bn * Nn];        // row sums of shifted exps
__device__ float g_scl[Vd];
__device__ float g_shf[Vd];

// ===========================================================================
// Helpers (portable ISA: sm_80-class mma.sync + cp.async only)
// ===========================================================================
__device__ __forceinline__ uint32_t smem_u32(const void* p) {
    uint32_t a;
    asm("{ .reg .u64 t; cvta.to.shared.u64 t, %1; cvt.u32.u64 %0, t; }" : "=r"(a) : "l"(p));
    return a;
}
__device__ __forceinline__ void cp_async16(uint32_t saddr, const void* gaddr) {
    asm volatile("cp.async.ca.shared.global [%0], [%1], 16;"
                 :: "r"(saddr), "l"(gaddr) : "memory");
}
__device__ __forceinline__ void cp_commit() {
    asm volatile("cp.async.commit_group;" ::: "memory");
}
__device__ __forceinline__ void cp_wait2() {
    asm volatile("cp.async.wait_group 2;" ::: "memory");
}
__device__ __forceinline__ void cp_wait1() {
    asm volatile("cp.async.wait_group 1;" ::: "memory");
}
__device__ __forceinline__ void cp_wait0() {
    asm volatile("cp.async.wait_group 0;" ::: "memory");
}
__device__ __forceinline__ void mma_bf16(float* d, const uint32_t* a, const uint32_t* b) {
    asm volatile(
        "mma.sync.aligned.m16n8k16.row.col.f32.bf16.bf16.f32 "
        "{%0,%1,%2,%3}, {%4,%5,%6,%7}, {%8,%9}, {%0,%1,%2,%3};"
        : "+f"(d[0]), "+f"(d[1]), "+f"(d[2]), "+f"(d[3])
        : "r"(a[0]), "r"(a[1]), "r"(a[2]), "r"(a[3]), "r"(b[0]), "r"(b[1]));
}
__device__ __forceinline__ void mma_f16(float* d, const uint32_t* a, const uint32_t* b) {
    asm volatile(
        "mma.sync.aligned.m16n8k16.row.col.f32.f16.f16.f32 "
        "{%0,%1,%2,%3}, {%4,%5,%6,%7}, {%8,%9}, {%0,%1,%2,%3};"
        : "+f"(d[0]), "+f"(d[1]), "+f"(d[2]), "+f"(d[3])
        : "r"(a[0]), "r"(a[1]), "r"(a[2]), "r"(a[3]), "r"(b[0]), "r"(b[1]));
}
__device__ __forceinline__ uint32_t lds_u32(const char* p) { return *(const uint32_t*)p; }
__device__ __forceinline__ uint32_t bfcat(__nv_bfloat16 lo, __nv_bfloat16 hi) {
    __nv_bfloat162 t; t.x = lo; t.y = hi;
    return *(uint32_t*)&t;
}
__device__ __forceinline__ uint32_t hfcat(__half lo, __half hi) {
    __half2 t; t.x = lo; t.y = hi;
    return *(uint32_t*)&t;
}

// ===========================================================================
// BN scale/shift precompute
// ===========================================================================
__global__ void prep_kernel(const float* __restrict__ gamma, const float* __restrict__ beta,
                            const float* __restrict__ mean,  const float* __restrict__ var) {
    int i = threadIdx.x;
    if (i < Vd) {
        float s = gamma[i] * rsqrtf(var[i] + 1e-5f);
        g_scl[i] = s;
        g_shf[i] = beta[i] - mean[i] * s;
    }
}

// ===========================================================================
// W split: [Wq;Wk] -> bf16 hi/lo
// ===========================================================================
__global__ __launch_bounds__(256) void wsplit_kernel(const float* __restrict__ Wq,
                                                     const float* __restrict__ Wk) {
    int id = blockIdx.x * 256 + threadIdx.x;
    int o = id >> 9, cc = id & 511;
    float v = (o < 64) ? Wq[o * Cc + cc] : Wk[(o - 64) * Cc + cc];
    __nv_bfloat16 h = __float2bfloat16(v);
    g_Wh[id] = h;
    g_Wl[id] = __float2bfloat16(v - __bfloat162float(h));
}

// ===========================================================================
// Wv -> fp16
// ===========================================================================
__global__ __launch_bounds__(256) void wvhalf_kernel(const float* __restrict__ Wv) {
    int id = blockIdx.x * 256 + threadIdx.x;     // 512*512
    g_Wvf[id] = __float2half(Wv[id]);
}

// ===========================================================================
// X split + transpose: x[b][c][n] fp32 -> [b][n][c]: bf16 hi/lo + fp16
// ===========================================================================
__global__ __launch_bounds__(256) void xsplit_kernel(const float* __restrict__ x) {
    __shared__ float t[32][33];
    const int b = blockIdx.z, n0 = blockIdx.x * 32, c0 = blockIdx.y * 32;
    const int tx = threadIdx.x & 31, ty = threadIdx.x >> 5;
    #pragma unroll
    for (int p = 0; p < 4; p++)
        t[ty + 8 * p][tx] = x[((size_t)b * Cc + c0 + ty + 8 * p) * Nn + n0 + tx];
    __syncthreads();
    #pragma unroll
    for (int p = 0; p < 4; p++) {
        float v = t[tx][ty + 8 * p];
        __nv_bfloat16 h = __float2bfloat16(v);
        __nv_bfloat16 l = __float2bfloat16(v - __bfloat162float(h));
        size_t idx = ((size_t)b * Nn + n0 + ty + 8 * p) * Cc + c0 + tx;
        g_Xh[idx] = h;
        g_Xl[idx] = l;
        g_Xf[idx] = __float2half(v);
    }
}

// ===========================================================================
// Q+K projection on mma.sync bf16 (3-term split)   (unchanged)
// ===========================================================================
static constexpr int QK_XH0 = 0,     QK_XH1 = 5120;
static constexpr int QK_XL0 = 10240, QK_XL1 = 15360;
static constexpr int QK_WH0 = 20480, QK_WH1 = 30720;
static constexpr int QK_WL0 = 40960, QK_WL1 = 51200;
static constexpr int QK_BYTES = 61440;

__device__ __forceinline__ void qk_stage(uint32_t sbase, int buf, int b, int n0, int kc) {
    const int t = threadIdx.x;
    const uint32_t xh = sbase + (buf ? QK_XH1 : QK_XH0);
    const uint32_t xl = sbase + (buf ? QK_XL1 : QK_XL0);
    const uint32_t wh = sbase + (buf ? QK_WH1 : QK_WH0);
    const uint32_t wl = sbase + (buf ? QK_WL1 : QK_WL0);
    {
        int r = t >> 2, c4 = t & 3;
        size_t src = ((size_t)b * Nn + n0 + r) * Cc + kc * 32 + c4 * 8;
        cp_async16(xh + r * 80 + c4 * 16, g_Xh + src);
        cp_async16(xl + r * 80 + c4 * 16, g_Xl + src);
    }
    #pragma unroll
    for (int p = 0; p < 2; p++) {
        int id = t + 256 * p, r = id >> 2, c4 = id & 3;
        size_t src = (size_t)r * Cc + kc * 32 + c4 * 8;
        cp_async16(wh + r * 80 + c4 * 16, g_Wh + src);
        cp_async16(wl + r * 80 + c4 * 16, g_Wl + src);
    }
}

__global__ __launch_bounds__(256) void qk_mma_kernel(const float* __restrict__ bq,
                                                     const float* __restrict__ bk) {
    extern __shared__ char smc[];
    const uint32_t sbase = smem_u32(smc);
    const int tid = threadIdx.x;
    const int wid = tid >> 5, lane = tid & 31;
    const int g = lane >> 2, c = lane & 3;
    const int wn = wid & 1, wo = wid >> 1;
    const int b  = blockIdx.z;
    const int n0 = blockIdx.x * 64;

    float acc[2][4][4] = {};

    qk_stage(sbase, 0, b, n0, 0);
    cp_commit();

    for (int kc = 0; kc < 16; kc++) {
        const int cur = kc & 1;
        if (kc + 1 < 16) {
            qk_stage(sbase, cur ^ 1, b, n0, kc + 1);
            cp_commit();
            cp_wait1();
        } else {
            cp_wait0();
        }
        __syncthreads();

        const char* XH = smc + (cur ? QK_XH1 : QK_XH0);
        const char* XL = smc + (cur ? QK_XL1 : QK_XL0);
        const char* WH = smc + (cur ? QK_WH1 : QK_WH0);
        const char* WL = smc + (cur ? QK_WL1 : QK_WL0);

        #pragma unroll
        for (int ks = 0; ks < 2; ks++) {
            uint32_t ah[2][4], al[2][4];
            #pragma unroll
            for (int i = 0; i < 2; i++) {
                const int off = (wn * 32 + i * 16 + g) * 80 + ks * 32 + c * 4;
                ah[i][0] = lds_u32(XH + off);
                ah[i][1] = lds_u32(XH + off + 8 * 80);
                ah[i][2] = lds_u32(XH + off + 16);
                ah[i][3] = lds_u32(XH + off + 8 * 80 + 16);
                al[i][0] = lds_u32(XL + off);
                al[i][1] = lds_u32(XL + off + 8 * 80);
                al[i][2] = lds_u32(XL + off + 16);
                al[i][3] = lds_u32(XL + off + 8 * 80 + 16);
            }
            uint32_t bh[4][2], bl[4][2];
            #pragma unroll
            for (int j = 0; j < 4; j++) {
                const int off = (wo * 32 + j * 8 + g) * 80 + ks * 32 + c * 4;
                bh[j][0] = lds_u32(WH + off);
                bh[j][1] = lds_u32(WH + off + 16);
                bl[j][0] = lds_u32(WL + off);
                bl[j][1] = lds_u32(WL + off + 16);
            }
            #pragma unroll
            for (int i = 0; i < 2; i++)
                #pragma unroll
                for (int j = 0; j < 4; j++) {
                    mma_bf16(acc[i][j], ah[i], bh[j]);
                    mma_bf16(acc[i][j], ah[i], bl[j]);
                    mma_bf16(acc[i][j], al[i], bh[j]);
                }
        }
        __syncthreads();
    }

    const int which = wo >> 1;
    __nv_bfloat16* dh = which ? g_Kh : g_Qh;
    __nv_bfloat16* dl = which ? g_Kl : g_Ql;
    const float* bias = which ? bk : bq;
    #pragma unroll
    for (int i = 0; i < 2; i++) {
        const int n_lo = n0 + wn * 32 + i * 16 + g;
        #pragma unroll
        for (int j = 0; j < 4; j++) {
            const int o = (wo * 32 + j * 8 + 2 * c) & 63;
            const float b0 = bias[o], b1 = bias[o + 1];
            float v00 = acc[i][j][0] + b0, v01 = acc[i][j][1] + b1;
            float v10 = acc[i][j][2] + b0, v11 = acc[i][j][3] + b1;
            __nv_bfloat16 h00 = __float2bfloat16(v00), h01 = __float2bfloat16(v01);
            __nv_bfloat16 h10 = __float2bfloat16(v10), h11 = __float2bfloat16(v11);
            __nv_bfloat16 l00 = __float2bfloat16(v00 - __bfloat162float(h00));
            __nv_bfloat16 l01 = __float2bfloat16(v01 - __bfloat162float(h01));
            __nv_bfloat16 l10 = __float2bfloat16(v10 - __bfloat162float(h10));
            __nv_bfloat16 l11 = __float2bfloat16(v11 - __bfloat162float(h11));
            size_t r0 = ((size_t)b * Nn + n_lo) * Kd + o;
            size_t r1 = ((size_t)b * Nn + n_lo + 8) * Kd + o;
            *(uint32_t*)&dh[r0] = bfcat(h00, h01);
            *(uint32_t*)&dh[r1] = bfcat(h10, h11);
            *(uint32_t*)&dl[r0] = bfcat(l00, l01);
            *(uint32_t*)&dl[r1] = bfcat(l10, l11);
        }
    }
}

// ===========================================================================
// V projection on single-pass fp16 mma.sync   (unchanged)
// ===========================================================================
static constexpr int VP_W0 = 0,     VP_W1 = 10240;
static constexpr int VP_X0 = 20480, VP_X1 = 30720;
static constexpr int VP_BYTES = 40960;

__device__ __forceinline__ void vproj_stage(uint32_t sbase, int buf, int b,
                                            int m0, int v0, int kc) {
    const int t = threadIdx.x;
    const uint32_t sW = sbase + (buf ? VP_W1 : VP_W0);
    const uint32_t sX = sbase + (buf ? VP_X1 : VP_X0);
    #pragma unroll
    for (int p = 0; p < 2; p++) {
        int id = t + 256 * p, r = id >> 2, c4 = id & 3;
        cp_async16(sW + r * 80 + c4 * 16,
                   g_Wvf + (size_t)(v0 + r) * Cc + kc * 32 + c4 * 8);
    }
    #pragma unroll
    for (int p = 0; p < 2; p++) {
        int id = t + 256 * p, r = id >> 2, c4 = id & 3;
        cp_async16(sX + r * 80 + c4 * 16,
                   g_Xf + ((size_t)b * Nn + m0 + r) * Cc + kc * 32 + c4 * 8);
    }
}

__global__ __launch_bounds__(256) void vproj_mma_kernel() {
    extern __shared__ char smc[];
    const uint32_t sbase = smem_u32(smc);
    const int tid = threadIdx.x;
    const int wid = tid >> 5, lane = tid & 31;
    const int g = lane >> 2, c = lane & 3;
    const int wn = wid & 1, wv = wid >> 1;
    const int b  = blockIdx.z;
    const int m0 = blockIdx.y * 128;
    const int v0 = blockIdx.x * 128;

    float acc[4][4][4] = {};

    vproj_stage(sbase, 0, b, m0, v0, 0);
    cp_commit();

    for (int kc = 0; kc < Cc / 32; kc++) {
        const int cur = kc & 1;
        if (kc + 1 < Cc / 32) {
            vproj_stage(sbase, cur ^ 1, b, m0, v0, kc + 1);
            cp_commit();
            cp_wait1();
        } else {
            cp_wait0();
        }
        __syncthreads();

        const char* Ws = smc + (cur ? VP_W1 : VP_W0);
        const char* Xs = smc + (cur ? VP_X1 : VP_X0);

        #pragma unroll
        for (int ks = 0; ks < 2; ks++) {
            uint32_t af[4][4];
            #pragma unroll
            for (int i = 0; i < 4; i++) {
                const int off = (wn * 64 + i * 16 + g) * 80 + ks * 32 + c * 4;
                af[i][0] = lds_u32(Ws + off);
                af[i][1] = lds_u32(Ws + off + 8 * 80);
                af[i][2] = lds_u32(Ws + off + 16);
                af[i][3] = lds_u32(Ws + off + 8 * 80 + 16);
            }
            uint32_t bf[4][2];
            #pragma unroll
            for (int j = 0; j < 4; j++) {
                const int off = (wv * 32 + j * 8 + g) * 80 + ks * 32 + c * 4;
                bf[j][0] = lds_u32(Xs + off);
                bf[j][1] = lds_u32(Xs + off + 16);
            }
            #pragma unroll
            for (int i = 0; i < 4; i++)
                #pragma unroll
                for (int j = 0; j < 4; j++)
                    mma_f16(acc[i][j], af[i], bf[j]);
        }
        __syncthreads();
    }

    const int mt = blockIdx.y * 2 + (wv >> 1);
    uint32_t* base = g_Vh + ((size_t)b * 64 + mt) * 16384;
    #pragma unroll
    for (int i = 0; i < 4; i++) {
        const int vg = v0 + wn * 64 + i * 16 + g;
        const float sg = g_scl[vg],     hg = g_shf[vg];
        const float s8 = g_scl[vg + 8], h8 = g_shf[vg + 8];
        const int vj = vg >> 3;
        #pragma unroll
        for (int j = 0; j < 4; j++) {
            const int kb = ((wv * 32 + j * 8) >> 4) & 3;
            const int lohi = j & 1;
            __half a0 = __float2half(fmaxf(fmaf(acc[i][j][0], sg, hg), 0.f));
            __half a1 = __float2half(fmaxf(fmaf(acc[i][j][1], sg, hg), 0.f));
            __half a2 = __float2half(fmaxf(fmaf(acc[i][j][2], s8, h8), 0.f));
            __half a3 = __float2half(fmaxf(fmaf(acc[i][j][3], s8, h8), 0.f));
            base[(size_t)kb * 4096 + (size_t)vj * 64 + lane * 2 + lohi]       = hfcat(a0, a1);
            base[(size_t)kb * 4096 + (size_t)(vj + 1) * 64 + lane * 2 + lohi] = hfcat(a2, a3);
        }
    }
}

// ===========================================================================
// Energy, FUSED max pass. Phase 1 now processes 128-row K-hi chunks (two
// 64-row halves in KH/KL buffer pairs, 2-deep pipeline) -> better MMA/LDS.
// Phase 2 unchanged (3-term, exp(l-M), fp16 packed A-frags + g_L).
// grid (Nn/64, Bn), block 256, warps 2(n) x 4(m).
// ===========================================================================
static constexpr int E_QH  = 0;
static constexpr int E_QL  = 9216;
static constexpr int E_KH0 = 18432;
static constexpr int E_KH1 = 27648;
static constexpr int E_KL0 = 36864;
static constexpr int E_KL1 = 46080;
static constexpr int E_BYTES = 55296;

__device__ __forceinline__ void e_stage128(uint32_t sbase, int par, size_t koff, int base) {
    // stage K-hi rows [base, base+128): rows 0-63 -> KH{par}, 64-127 -> KL{par}
    const int t = threadIdx.x;
    const uint32_t kh = sbase + (par ? E_KH1 : E_KH0);
    const uint32_t kl = sbase + (par ? E_KL1 : E_KL0);
    #pragma unroll
    for (int p = 0; p < 4; p++) {
        int id = t + 256 * p, r = id >> 3, c8 = id & 7;   // r 0..127
        uint32_t dst = (r < 64 ? kh + r * 144 : kl + (r - 64) * 144) + c8 * 16;
        cp_async16(dst, g_Kh + koff + (size_t)(base + r) * Kd + c8 * 8);
    }
}

__global__ __launch_bounds__(256) void energy_mma_kernel() {
    extern __shared__ char smc[];
    __shared__ float sR[4][64];
    const uint32_t sbase = smem_u32(smc);
    const int tid = threadIdx.x;
    const int wid = tid >> 5, lane = tid & 31;
    const int g = lane >> 2, c = lane & 3;
    const int wn = wid & 1, wv = wid >> 1;
    const int b  = blockIdx.y;
    const int n0 = blockIdx.x * 64;
    const int nt = blockIdx.x >> 1;
    const int half = blockIdx.x & 1;

    const size_t qoff = ((size_t)b * Nn + n0) * Kd;
    const size_t koff = (size_t)b * Nn * Kd;

    // ---- Stage Q (hi+lo), resident for both phases ----
    #pragma unroll
    for (int p = 0; p < 2; p++) {
        int id = tid + 256 * p, r = id >> 3, c8 = id & 7;
        cp_async16(sbase + E_QH + r * 144 + c8 * 16, g_Qh + qoff + (size_t)r * Kd + c8 * 8);
        cp_async16(sbase + E_QL + r * 144 + c8 * 16, g_Ql + qoff + (size_t)r * Kd + c8 * 8);
    }
    e_stage128(sbase, 0, koff, 0);
    cp_commit();

    // =============== Phase 1: exact row max (hi-only), 128-row chunks ======
    float mx[2][2] = { { -1e30f, -1e30f }, { -1e30f, -1e30f } };

    for (int mc2 = 0; mc2 < 32; mc2++) {
        const int cur = mc2 & 1;
        if (mc2 + 1 < 32) {
            e_stage128(sbase, cur ^ 1, koff, (mc2 + 1) * 128);
            cp_commit();
            cp_wait1();
        } else {
            cp_wait0();
        }
        __syncthreads();

        const char* QH = smc + E_QH;
        const char* KA = smc + (cur ? E_KH1 : E_KH0);
        const char* KB = smc + (cur ? E_KL1 : E_KL0);

        float acc[2][4][4] = {};
        #pragma unroll
        for (int ks = 0; ks < 4; ks++) {
            uint32_t ah[2][4];
            #pragma unroll
            for (int i = 0; i < 2; i++) {
                const int off = (wn * 32 + i * 16 + g) * 144 + ks * 32 + c * 4;
                ah[i][0] = lds_u32(QH + off);
                ah[i][1] = lds_u32(QH + off + 8 * 144);
                ah[i][2] = lds_u32(QH + off + 16);
                ah[i][3] = lds_u32(QH + off + 8 * 144 + 16);
            }
            uint32_t bh[4][2];
            #pragma unroll
            for (int j = 0; j < 2; j++) {
                const int off = (wv * 16 + j * 8 + g) * 144 + ks * 32 + c * 4;
                bh[j][0]     = lds_u32(KA + off);
                bh[j][1]     = lds_u32(KA + off + 16);
                bh[j + 2][0] = lds_u32(KB + off);
                bh[j + 2][1] = lds_u32(KB + off + 16);
            }
            #pragma unroll
            for (int i = 0; i < 2; i++)
                #pragma unroll
                for (int j = 0; j < 4; j++)
                    mma_bf16(acc[i][j], ah[i], bh[j]);
        }
        __syncthreads();

        #pragma unroll
        for (int i = 0; i < 2; i++)
            #pragma unroll
            for (int j = 0; j < 4; j++) {
                mx[i][0] = fmaxf(mx[i][0], fmaxf(acc[i][j][0], acc[i][j][1]));
                mx[i][1] = fmaxf(mx[i][1], fmaxf(acc[i][j][2], acc[i][j][3]));
            }
    }

    #pragma unroll
    for (int i = 0; i < 2; i++)
        #pragma unroll
        for (int r = 0; r < 2; r++) {
            float v = mx[i][r];
            v = fmaxf(v, __shfl_xor_sync(0xffffffffu, v, 1));
            v = fmaxf(v, __shfl_xor_sync(0xffffffffu, v, 2));
            mx[i][r] = v;
        }
    if (c == 0) {
        #pragma unroll
        for (int i = 0; i < 2; i++) {
            sR[wv][wn * 32 + i * 16 + g]     = mx[i][0];
            sR[wv][wn * 32 + i * 16 + g + 8] = mx[i][1];
        }
    }
    __syncthreads();

    float Mv[2][2];
    #pragma unroll
    for (int i = 0; i < 2; i++) {
        const int r0 = wn * 32 + i * 16 + g;
        Mv[i][0] = fmaxf(fmaxf(sR[0][r0],     sR[1][r0]),     fmaxf(sR[2][r0],     sR[3][r0]));
        Mv[i][1] = fmaxf(fmaxf(sR[0][r0 + 8], sR[1][r0 + 8]), fmaxf(sR[2][r0 + 8], sR[3][r0 + 8]));
    }
    __syncthreads();

    // =============== Phase 2: full 3-term energy + exp ===============
    #pragma unroll
    for (int p = 0; p < 2; p++) {
        int id = tid + 256 * p, r = id >> 3, c8 = id & 7;
        cp_async16(sbase + E_KH0 + r * 144 + c8 * 16, g_Kh + koff + (size_t)r * Kd + c8 * 8);
        cp_async16(sbase + E_KL0 + r * 144 + c8 * 16, g_Kl + koff + (size_t)r * Kd + c8 * 8);
    }
    cp_commit();

    float rsum[2][2] = {};

    for (int mc = 0; mc < 64; mc++) {
        const int cur = mc & 1;
        if (mc + 1 < 64) {
            const uint32_t kh = sbase + ((mc + 1) & 1 ? E_KH1 : E_KH0);
            const uint32_t kl = sbase + ((mc + 1) & 1 ? E_KL1 : E_KL0);
            #pragma unroll
            for (int p = 0; p < 2; p++) {
                int id = tid + 256 * p, r = id >> 3, c8 = id & 7;
                cp_async16(kh + r * 144 + c8 * 16,
                           g_Kh + koff + (size_t)((mc + 1) * 64 + r) * Kd + c8 * 8);
                cp_async16(kl + r * 144 + c8 * 16,
                           g_Kl + koff + (size_t)((mc + 1) * 64 + r) * Kd + c8 * 8);
            }
            cp_commit();
            cp_wait1();
        } else {
            cp_wait0();
        }
        __syncthreads();

        const char* QH = smc + E_QH;
        const char* QL = smc + E_QL;
        const char* KH = smc + (cur ? E_KH1 : E_KH0);
        const char* KL = smc + (cur ? E_KL1 : E_KL0);

        float acc[2][2][4] = {};
        #pragma unroll
        for (int ks = 0; ks < 4; ks++) {
            uint32_t ah[2][4], al[2][4];
            #pragma unroll
            for (int i = 0; i < 2; i++) {
                const int off = (wn * 32 + i * 16 + g) * 144 + ks * 32 + c * 4;
                ah[i][0] = lds_u32(QH + off);
                ah[i][1] = lds_u32(QH + off + 8 * 144);
                ah[i][2] = lds_u32(QH + off + 16);
                ah[i][3] = lds_u32(QH + off + 8 * 144 + 16);
                al[i][0] = lds_u32(QL + off);
                al[i][1] = lds_u32(QL + off + 8 * 144);
                al[i][2] = lds_u32(QL + off + 16);
                al[i][3] = lds_u32(QL + off + 8 * 144 + 16);
            }
            uint32_t bh[2][2], bl[2][2];
            #pragma unroll
            for (int j = 0; j < 2; j++) {
                const int off = (wv * 16 + j * 8 + g) * 144 + ks * 32 + c * 4;
                bh[j][0] = lds_u32(KH + off);
                bh[j][1] = lds_u32(KH + off + 16);
                bl[j][0] = lds_u32(KL + off);
                bl[j][1] = lds_u32(KL + off + 16);
            }
            #pragma unroll
            for (int i = 0; i < 2; i++)
                #pragma unroll
                for (int j = 0; j < 2; j++) {
                    mma_bf16(acc[i][j], ah[i], bh[j]);
                    mma_bf16(acc[i][j], ah[i], bl[j]);
                    mma_bf16(acc[i][j], al[i], bh[j]);
                }
        }
        __syncthreads();

        const size_t tile0 = (((size_t)b * 32 + nt) * 64 + mc) * 4096;
        #pragma unroll
        for (int i = 0; i < 2; i++) {
            const int i_blk = half * 4 + wn * 2 + i;
            __half h[2][4];
            #pragma unroll
            for (int j = 0; j < 2; j++) {
                h[j][0] = __float2half(__expf(acc[i][j][0] - Mv[i][0]));
                h[j][1] = __float2half(__expf(acc[i][j][1] - Mv[i][0]));
                h[j][2] = __float2half(__expf(acc[i][j][2] - Mv[i][1]));
                h[j][3] = __float2half(__expf(acc[i][j][3] - Mv[i][1]));
                rsum[i][0] += __half2float(h[j][0]) + __half2float(h[j][1]);
                rsum[i][1] += __half2float(h[j][2]) + __half2float(h[j][3]);
            }
            uint4 w4;
            w4.x = hfcat(h[0][0], h[0][1]);
            w4.y = hfcat(h[0][2], h[0][3]);
            w4.z = hfcat(h[1][0], h[1][1]);
            w4.w = hfcat(h[1][2], h[1][3]);
            *(uint4*)&g_Pf[tile0 + (size_t)((i_blk * 4 + wv) * 128 + lane * 4)] = w4;
        }
    }

    #pragma unroll
    for (int i = 0; i < 2; i++)
        #pragma unroll
        for (int r = 0; r < 2; r++) {
            float v = rsum[i][r];
            v += __shfl_xor_sync(0xffffffffu, v, 1);
            v += __shfl_xor_sync(0xffffffffu, v, 2);
            rsum[i][r] = v;
        }
    if (c == 0) {
        #pragma unroll
        for (int i = 0; i < 2; i++) {
            sR[wv][wn * 32 + i * 16 + g]     = rsum[i][0];
            sR[wv][wn * 32 + i * 16 + g + 8] = rsum[i][1];
        }
    }
    __syncthreads();
    if (tid < 64)
        g_L[(size_t)b * Nn + n0 + tid] = sR[0][tid] + sR[1][tid] + sR[2][tid] + sR[3][tid];
}

// ===========================================================================
// PV GEMM on fp16 m16n8k16, packed fragments, K-chunk 64, 3-STAGE pipeline:
//   out[b][v][n] = (1/L[n]) * sum_m P[n][m] V[m][v]
// Block 128(n) x 128(v), warp 64x32 (2x4 warps).
// SMEM u32: A stages @ {0,4096,8192} (16KB), B @ {12288,16384,20480}. 96KB.
// ===========================================================================
static constexpr int AV_BYTES = 98304;

__device__ __forceinline__ void av_stage(uint32_t sbase, int s,
                                         const uint32_t* gA, const uint32_t* gB,
                                         int v0j, int mt) {
    const int t = threadIdx.x;
    const uint32_t sA = sbase + (uint32_t)(s * 4096) * 4;
    const uint32_t sB = sbase + (uint32_t)(12288 + s * 4096) * 4;
    const uint32_t* gAt = gA + (size_t)mt * 4096;
    const uint32_t* gBt = gB + (size_t)mt * 16384 + (size_t)v0j * 64;
    #pragma unroll
    for (int p = 0; p < 4; p++) {   // A: linear 1024 x 16B
        int id = t + 256 * p;
        cp_async16(sA + (uint32_t)id * 16, gAt + id * 4);
    }
    #pragma unroll
    for (int p = 0; p < 4; p++) {   // B: 4 kb x 16 vj x 64 u32
        int id = t + 256 * p, kb = id >> 8, rem = id & 255;
        int vjl = rem >> 4, q = rem & 15;
        cp_async16(sB + (uint32_t)(kb * 1024 + vjl * 64 + q * 4) * 4,
                   gBt + (size_t)kb * 4096 + (size_t)vjl * 64 + q * 4);
    }
}

__global__ __launch_bounds__(256, 2) void av_mma_kernel(float* __restrict__ out) {
    extern __shared__ uint32_t smu[];
    const uint32_t sbase = smem_u32(smu);
    const int tid  = threadIdx.x;
    const int wid  = tid >> 5, lane = tid & 31;
    const int g = lane >> 2, c = lane & 3;
    const int wn = wid & 1, wv = wid >> 1;
    const int b  = blockIdx.z;
    const int nt = blockIdx.y;
    const int n0 = nt * 128;
    const int v0 = blockIdx.x * 128;

    const uint32_t* gA = g_Pf + (((size_t)b * 32 + nt) * 64) * 4096;
    const uint32_t* gB = g_Vh + ((size_t)b * 64) * 16384;

    float acc[4][4][4] = {};

    av_stage(sbase, 0, gA, gB, v0 >> 3, 0); cp_commit();
    av_stage(sbase, 1, gA, gB, v0 >> 3, 1); cp_commit();

    for (int mt = 0; mt < 64; mt++) {
        const int s = mt % 3;
        if (mt + 2 < 64) {
            av_stage(sbase, (mt + 2) % 3, gA, gB, v0 >> 3, mt + 2);
            cp_commit();
            cp_wait2();
        } else if (mt + 1 < 64) {
            cp_wait1();
        } else {
            cp_wait0();
        }
        __syncthreads();

        const uint32_t* As = smu + s * 4096;
        const uint32_t* Bs = smu + 12288 + s * 4096;

        #pragma unroll
        for (int kb = 0; kb < 4; kb++) {
            uint4 af[4];
            #pragma unroll
            for (int i = 0; i < 4; i++)
                af[i] = *(const uint4*)(As + (wn * 4 + i) * 512 + kb * 128 + lane * 4);
            uint2 bfr[4];
            #pragma unroll
            for (int j = 0; j < 4; j++)
                bfr[j] = *(const uint2*)(Bs + kb * 1024 + (wv * 4 + j) * 64 + lane * 2);
            #pragma unroll
            for (int i = 0; i < 4; i++)
                #pragma unroll
                for (int j = 0; j < 4; j++)
                    mma_f16(acc[i][j], (const uint32_t*)&af[i], (const uint32_t*)&bfr[j]);
        }
        __syncthreads();
    }

    #pragma unroll
    for (int i = 0; i < 4; i++) {
        const int n_lo = n0 + wn * 64 + i * 16 + g;
        const float linv_lo = 1.0f / g_L[(size_t)b * Nn + n_lo];
        const float linv_hi = 1.0f / g_L[(size_t)b * Nn + n_lo + 8];
        #pragma unroll
        for (int j = 0; j < 4; j++) {
            const int v = v0 + wv * 32 + j * 8 + c * 2;
            float* o0p = out + ((size_t)b * Vd + v)     * Nn + n_lo;
            float* o1p = out + ((size_t)b * Vd + v + 1) * Nn + n_lo;
            o0p[0] = acc[i][j][0] * linv_lo;
            o1p[0] = acc[i][j][1] * linv_lo;
            o0p[8] = acc[i][j][2] * linv_hi;
            o1p[8] = acc[i][j][3] * linv_hi;
        }
    }
}

// ===========================================================================
// Launch: two-stream graph. s0: prep/wsplit/xsplit -> qk -> energy -> (join) av
//         s2: (fork) wvhalf -> (after xsplit) vproj -> join
// ===========================================================================
extern "C" void kernel_launch(void* const* d_in, const int* in_sizes, int n_in,
                              void* d_out, int out_size) {
    const float* x     = (const float*)d_in[0];
    const float* Wq    = (const float*)d_in[1];
    const float* bq    = (const float*)d_in[2];
    const float* Wk    = (const float*)d_in[3];
    const float* bk    = (const float*)d_in[4];
    const float* Wv    = (const float*)d_in[5];
    const float* gamma = (const float*)d_in[6];
    const float* beta  = (const float*)d_in[7];
    const float* mean  = (const float*)d_in[8];
    const float* var   = (const float*)d_in[9];
    float* out = (float*)d_out;

    static cudaStream_t s2 = nullptr;
    static cudaEvent_t ev_fork = nullptr, ev_x = nullptr, ev_join = nullptr;
    static int inited = 0;
    if (!inited) {
        cudaFuncSetAttribute(qk_mma_kernel,
                             cudaFuncAttributeMaxDynamicSharedMemorySize, QK_BYTES);
        cudaFuncSetAttribute(vproj_mma_kernel,
                             cudaFuncAttributeMaxDynamicSharedMemorySize, VP_BYTES);
        cudaFuncSetAttribute(energy_mma_kernel,
                             cudaFuncAttributeMaxDynamicSharedMemorySize, E_BYTES);
        cudaFuncSetAttribute(av_mma_kernel,
                             cudaFuncAttributeMaxDynamicSharedMemorySize, AV_BYTES);
        cudaStreamCreateWithFlags(&s2, cudaStreamNonBlocking);
        cudaEventCreateWithFlags(&ev_fork, cudaEventDisableTiming);
        cudaEventCreateWithFlags(&ev_x,    cudaEventDisableTiming);
        cudaEventCreateWithFlags(&ev_join, cudaEventDisableTiming);
        inited = 1;
    }

    // s0 work
    prep_kernel<<<1, 512>>>(gamma, beta, mean, var);
    cudaEventRecord(ev_fork, 0);
    wsplit_kernel<<<256, 256>>>(Wq, Wk);
    xsplit_kernel<<<dim3(Nn / 32, Cc / 32, Bn), 256>>>(x);
    cudaEventRecord(ev_x, 0);

    // s2 branch: wvhalf (independent), then vproj after xsplit
    cudaStreamWaitEvent(s2, ev_fork, 0);
    wvhalf_kernel<<<1024, 256, 0, s2>>>(Wv);
    cudaStreamWaitEvent(s2, ev_x, 0);
    vproj_mma_kernel<<<dim3(Vd / 128, Nn / 128, Bn), 256, VP_BYTES, s2>>>();
    cudaEventRecord(ev_join, s2);

    // s0 continues: qk -> energy
    qk_mma_kernel<<<dim3(Nn / 64, 1, Bn), 256, QK_BYTES>>>(bq, bk);
    energy_mma_kernel<<<dim3(Nn / 64, Bn), 256, E_BYTES>>>();

    // join and run av
    cudaStreamWaitEvent(0, ev_join, 0);
    av_mma_kernel<<<dim3(Vd / 128, Nn / 128, Bn), 256, AV_BYTES>>>(out);
}

// round 17
// speedup vs baseline: 1.0415x; 1.0025x over previous
#include <cuda_runtime.h>
#include <cuda_bf16.h>
#include <cuda_fp16.h>
#include <cstdint>
#include <cstddef>

static constexpr int Bn = 8;
static constexpr int Cc = 512;
static constexpr int Nn = 4096;   // H*W
static constexpr int Kd = 64;
static constexpr int Vd = 512;

// Scratch (device globals)
__device__ __nv_bfloat16 g_Xh[(size_t)Bn * Nn * Cc];   // x transposed [b][n][c] bf16 hi
__device__ __nv_bfloat16 g_Xl[(size_t)Bn * Nn * Cc];
__device__ __half        g_Xf[(size_t)Bn * Nn * Cc];   // x transposed [b][n][c] fp16
__device__ __nv_bfloat16 g_Wh[128 * Cc];               // [Wq;Wk]
__device__ __nv_bfloat16 g_Wl[128 * Cc];
__device__ __half        g_Wvf[Vd * Cc];               // Wv fp16 [v][c]
__device__ __nv_bfloat16 g_Qh[(size_t)Bn * Nn * Kd];
__device__ __nv_bfloat16 g_Ql[(size_t)Bn * Nn * Kd];
__device__ __nv_bfloat16 g_Kh[(size_t)Bn * Nn * Kd];
__device__ __nv_bfloat16 g_Kl[(size_t)Bn * Nn * Kd];
// V fp16 packed as av B-fragments: per [b][mt 0..63]: [kb 0..3][vj 0..63][lane][2] u32
__device__ uint32_t g_Vh[(size_t)Bn * 64 * 16384];
// P fp16 packed as av A-fragments: per [b][nt 0..31][mt 0..63]:
//   [i_blk 0..7][kb 0..3][lane 0..31][4] u32   (4096 u32 = 16KB per tile)
__device__ uint32_t g_Pf[(size_t)Bn * 32 * 64 * 4096];
__device__ float g_L [(size_t)Bn * Nn];        // row sums of shifted exps
__device__ float g_scl[Vd];
__device__ float g_shf[Vd];

// ===========================================================================
// Helpers (portable ISA: sm_80-class mma.sync + cp.async only)
// ===========================================================================
__device__ __forceinline__ uint32_t smem_u32(const void* p) {
    uint32_t a;
    asm("{ .reg .u64 t; cvta.to.shared.u64 t, %1; cvt.u32.u64 %0, t; }" : "=r"(a) : "l"(p));
    return a;
}
__device__ __forceinline__ void cp_async16(uint32_t saddr, const void* gaddr) {
    asm volatile("cp.async.ca.shared.global [%0], [%1], 16;"
                 :: "r"(saddr), "l"(gaddr) : "memory");
}
__device__ __forceinline__ void cp_commit() {
    asm volatile("cp.async.commit_group;" ::: "memory");
}
__device__ __forceinline__ void cp_wait2() {
    asm volatile("cp.async.wait_group 2;" ::: "memory");
}
__device__ __forceinline__ void cp_wait1() {
    asm volatile("cp.async.wait_group 1;" ::: "memory");
}
__device__ __forceinline__ void cp_wait0() {
    asm volatile("cp.async.wait_group 0;" ::: "memory");
}
__device__ __forceinline__ void mma_bf16(float* d, const uint32_t* a, const uint32_t* b) {
    asm volatile(
        "mma.sync.aligned.m16n8k16.row.col.f32.bf16.bf16.f32 "
        "{%0,%1,%2,%3}, {%4,%5,%6,%7}, {%8,%9}, {%0,%1,%2,%3};"
        : "+f"(d[0]), "+f"(d[1]), "+f"(d[2]), "+f"(d[3])
        : "r"(a[0]), "r"(a[1]), "r"(a[2]), "r"(a[3]), "r"(b[0]), "r"(b[1]));
}
__device__ __forceinline__ void mma_f16(float* d, const uint32_t* a, const uint32_t* b) {
    asm volatile(
        "mma.sync.aligned.m16n8k16.row.col.f32.f16.f16.f32 "
        "{%0,%1,%2,%3}, {%4,%5,%6,%7}, {%8,%9}, {%0,%1,%2,%3};"
        : "+f"(d[0]), "+f"(d[1]), "+f"(d[2]), "+f"(d[3])
        : "r"(a[0]), "r"(a[1]), "r"(a[2]), "r"(a[3]), "r"(b[0]), "r"(b[1]));
}
__device__ __forceinline__ uint32_t lds_u32(const char* p) { return *(const uint32_t*)p; }
__device__ __forceinline__ uint32_t bfcat(__nv_bfloat16 lo, __nv_bfloat16 hi) {
    __nv_bfloat162 t; t.x = lo; t.y = hi;
    return *(uint32_t*)&t;
}
__device__ __forceinline__ uint32_t hfcat(__half lo, __half hi) {
    __half2 t; t.x = lo; t.y = hi;
    return *(uint32_t*)&t;
}

// ===========================================================================
// Fused prep: BN scale/shift + [Wq;Wk] bf16 hi/lo split + Wv fp16
// grid 1024 x 256 (id covers Wv domain 512*512)
// ===========================================================================
__global__ __launch_bounds__(256) void prep_all_kernel(
    const float* __restrict__ gamma, const float* __restrict__ beta,
    const float* __restrict__ mean,  const float* __restrict__ var,
    const float* __restrict__ Wq,    const float* __restrict__ Wk,
    const float* __restrict__ Wv) {
    int id = blockIdx.x * 256 + threadIdx.x;
    g_Wvf[id] = __float2half(Wv[id]);
    if (id < 128 * Cc) {
        int o = id >> 9, cc = id & 511;
        float v = (o < 64) ? Wq[o * Cc + cc] : Wk[(o - 64) * Cc + cc];
        __nv_bfloat16 h = __float2bfloat16(v);
        g_Wh[id] = h;
        g_Wl[id] = __float2bfloat16(v - __bfloat162float(h));
    }
    if (id < Vd) {
        float s = gamma[id] * rsqrtf(var[id] + 1e-5f);
        g_scl[id] = s;
        g_shf[id] = beta[id] - mean[id] * s;
    }
}

// ===========================================================================
// X split + transpose: x[b][c][n] fp32 -> [b][n][c]: bf16 hi/lo + fp16
// ===========================================================================
__global__ __launch_bounds__(256) void xsplit_kernel(const float* __restrict__ x) {
    __shared__ float t[32][33];
    const int b = blockIdx.z, n0 = blockIdx.x * 32, c0 = blockIdx.y * 32;
    const int tx = threadIdx.x & 31, ty = threadIdx.x >> 5;
    #pragma unroll
    for (int p = 0; p < 4; p++)
        t[ty + 8 * p][tx] = x[((size_t)b * Cc + c0 + ty + 8 * p) * Nn + n0 + tx];
    __syncthreads();
    #pragma unroll
    for (int p = 0; p < 4; p++) {
        float v = t[tx][ty + 8 * p];
        __nv_bfloat16 h = __float2bfloat16(v);
        __nv_bfloat16 l = __float2bfloat16(v - __bfloat162float(h));
        size_t idx = ((size_t)b * Nn + n0 + ty + 8 * p) * Cc + c0 + tx;
        g_Xh[idx] = h;
        g_Xl[idx] = l;
        g_Xf[idx] = __float2half(v);
    }
}

// ===========================================================================
// Q+K projection on mma.sync bf16 (3-term split)   (unchanged)
// ===========================================================================
static constexpr int QK_XH0 = 0,     QK_XH1 = 5120;
static constexpr int QK_XL0 = 10240, QK_XL1 = 15360;
static constexpr int QK_WH0 = 20480, QK_WH1 = 30720;
static constexpr int QK_WL0 = 40960, QK_WL1 = 51200;
static constexpr int QK_BYTES = 61440;

__device__ __forceinline__ void qk_stage(uint32_t sbase, int buf, int b, int n0, int kc) {
    const int t = threadIdx.x;
    const uint32_t xh = sbase + (buf ? QK_XH1 : QK_XH0);
    const uint32_t xl = sbase + (buf ? QK_XL1 : QK_XL0);
    const uint32_t wh = sbase + (buf ? QK_WH1 : QK_WH0);
    const uint32_t wl = sbase + (buf ? QK_WL1 : QK_WL0);
    {
        int r = t >> 2, c4 = t & 3;
        size_t src = ((size_t)b * Nn + n0 + r) * Cc + kc * 32 + c4 * 8;
        cp_async16(xh + r * 80 + c4 * 16, g_Xh + src);
        cp_async16(xl + r * 80 + c4 * 16, g_Xl + src);
    }
    #pragma unroll
    for (int p = 0; p < 2; p++) {
        int id = t + 256 * p, r = id >> 2, c4 = id & 3;
        size_t src = (size_t)r * Cc + kc * 32 + c4 * 8;
        cp_async16(wh + r * 80 + c4 * 16, g_Wh + src);
        cp_async16(wl + r * 80 + c4 * 16, g_Wl + src);
    }
}

__global__ __launch_bounds__(256) void qk_mma_kernel(const float* __restrict__ bq,
                                                     const float* __restrict__ bk) {
    extern __shared__ char smc[];
    const uint32_t sbase = smem_u32(smc);
    const int tid = threadIdx.x;
    const int wid = tid >> 5, lane = tid & 31;
    const int g = lane >> 2, c = lane & 3;
    const int wn = wid & 1, wo = wid >> 1;
    const int b  = blockIdx.z;
    const int n0 = blockIdx.x * 64;

    float acc[2][4][4] = {};

    qk_stage(sbase, 0, b, n0, 0);
    cp_commit();

    for (int kc = 0; kc < 16; kc++) {
        const int cur = kc & 1;
        if (kc + 1 < 16) {
            qk_stage(sbase, cur ^ 1, b, n0, kc + 1);
            cp_commit();
            cp_wait1();
        } else {
            cp_wait0();
        }
        __syncthreads();

        const char* XH = smc + (cur ? QK_XH1 : QK_XH0);
        const char* XL = smc + (cur ? QK_XL1 : QK_XL0);
        const char* WH = smc + (cur ? QK_WH1 : QK_WH0);
        const char* WL = smc + (cur ? QK_WL1 : QK_WL0);

        #pragma unroll
        for (int ks = 0; ks < 2; ks++) {
            uint32_t ah[2][4], al[2][4];
            #pragma unroll
            for (int i = 0; i < 2; i++) {
                const int off = (wn * 32 + i * 16 + g) * 80 + ks * 32 + c * 4;
                ah[i][0] = lds_u32(XH + off);
                ah[i][1] = lds_u32(XH + off + 8 * 80);
                ah[i][2] = lds_u32(XH + off + 16);
                ah[i][3] = lds_u32(XH + off + 8 * 80 + 16);
                al[i][0] = lds_u32(XL + off);
                al[i][1] = lds_u32(XL + off + 8 * 80);
                al[i][2] = lds_u32(XL + off + 16);
                al[i][3] = lds_u32(XL + off + 8 * 80 + 16);
            }
            uint32_t bh[4][2], bl[4][2];
            #pragma unroll
            for (int j = 0; j < 4; j++) {
                const int off = (wo * 32 + j * 8 + g) * 80 + ks * 32 + c * 4;
                bh[j][0] = lds_u32(WH + off);
                bh[j][1] = lds_u32(WH + off + 16);
                bl[j][0] = lds_u32(WL + off);
                bl[j][1] = lds_u32(WL + off + 16);
            }
            #pragma unroll
            for (int i = 0; i < 2; i++)
                #pragma unroll
                for (int j = 0; j < 4; j++) {
                    mma_bf16(acc[i][j], ah[i], bh[j]);
                    mma_bf16(acc[i][j], ah[i], bl[j]);
                    mma_bf16(acc[i][j], al[i], bh[j]);
                }
        }
        __syncthreads();
    }

    const int which = wo >> 1;
    __nv_bfloat16* dh = which ? g_Kh : g_Qh;
    __nv_bfloat16* dl = which ? g_Kl : g_Ql;
    const float* bias = which ? bk : bq;
    #pragma unroll
    for (int i = 0; i < 2; i++) {
        const int n_lo = n0 + wn * 32 + i * 16 + g;
        #pragma unroll
        for (int j = 0; j < 4; j++) {
            const int o = (wo * 32 + j * 8 + 2 * c) & 63;
            const float b0 = bias[o], b1 = bias[o + 1];
            float v00 = acc[i][j][0] + b0, v01 = acc[i][j][1] + b1;
            float v10 = acc[i][j][2] + b0, v11 = acc[i][j][3] + b1;
            __nv_bfloat16 h00 = __float2bfloat16(v00), h01 = __float2bfloat16(v01);
            __nv_bfloat16 h10 = __float2bfloat16(v10), h11 = __float2bfloat16(v11);
            __nv_bfloat16 l00 = __float2bfloat16(v00 - __bfloat162float(h00));
            __nv_bfloat16 l01 = __float2bfloat16(v01 - __bfloat162float(h01));
            __nv_bfloat16 l10 = __float2bfloat16(v10 - __bfloat162float(h10));
            __nv_bfloat16 l11 = __float2bfloat16(v11 - __bfloat162float(h11));
            size_t r0 = ((size_t)b * Nn + n_lo) * Kd + o;
            size_t r1 = ((size_t)b * Nn + n_lo + 8) * Kd + o;
            *(uint32_t*)&dh[r0] = bfcat(h00, h01);
            *(uint32_t*)&dh[r1] = bfcat(h10, h11);
            *(uint32_t*)&dl[r0] = bfcat(l00, l01);
            *(uint32_t*)&dl[r1] = bfcat(l10, l11);
        }
    }
}

// ===========================================================================
// V projection on single-pass fp16 mma.sync   (unchanged)
// ===========================================================================
static constexpr int VP_W0 = 0,     VP_W1 = 10240;
static constexpr int VP_X0 = 20480, VP_X1 = 30720;
static constexpr int VP_BYTES = 40960;

__device__ __forceinline__ void vproj_stage(uint32_t sbase, int buf, int b,
                                            int m0, int v0, int kc) {
    const int t = threadIdx.x;
    const uint32_t sW = sbase + (buf ? VP_W1 : VP_W0);
    const uint32_t sX = sbase + (buf ? VP_X1 : VP_X0);
    #pragma unroll
    for (int p = 0; p < 2; p++) {
        int id = t + 256 * p, r = id >> 2, c4 = id & 3;
        cp_async16(sW + r * 80 + c4 * 16,
                   g_Wvf + (size_t)(v0 + r) * Cc + kc * 32 + c4 * 8);
    }
    #pragma unroll
    for (int p = 0; p < 2; p++) {
        int id = t + 256 * p, r = id >> 2, c4 = id & 3;
        cp_async16(sX + r * 80 + c4 * 16,
                   g_Xf + ((size_t)b * Nn + m0 + r) * Cc + kc * 32 + c4 * 8);
    }
}

__global__ __launch_bounds__(256) void vproj_mma_kernel() {
    extern __shared__ char smc[];
    const uint32_t sbase = smem_u32(smc);
    const int tid = threadIdx.x;
    const int wid = tid >> 5, lane = tid & 31;
    const int g = lane >> 2, c = lane & 3;
    const int wn = wid & 1, wv = wid >> 1;
    const int b  = blockIdx.z;
    const int m0 = blockIdx.y * 128;
    const int v0 = blockIdx.x * 128;

    float acc[4][4][4] = {};

    vproj_stage(sbase, 0, b, m0, v0, 0);
    cp_commit();

    for (int kc = 0; kc < Cc / 32; kc++) {
        const int cur = kc & 1;
        if (kc + 1 < Cc / 32) {
            vproj_stage(sbase, cur ^ 1, b, m0, v0, kc + 1);
            cp_commit();
            cp_wait1();
        } else {
            cp_wait0();
        }
        __syncthreads();

        const char* Ws = smc + (cur ? VP_W1 : VP_W0);
        const char* Xs = smc + (cur ? VP_X1 : VP_X0);

        #pragma unroll
        for (int ks = 0; ks < 2; ks++) {
            uint32_t af[4][4];
            #pragma unroll
            for (int i = 0; i < 4; i++) {
                const int off = (wn * 64 + i * 16 + g) * 80 + ks * 32 + c * 4;
                af[i][0] = lds_u32(Ws + off);
                af[i][1] = lds_u32(Ws + off + 8 * 80);
                af[i][2] = lds_u32(Ws + off + 16);
                af[i][3] = lds_u32(Ws + off + 8 * 80 + 16);
            }
            uint32_t bf[4][2];
            #pragma unroll
            for (int j = 0; j < 4; j++) {
                const int off = (wv * 32 + j * 8 + g) * 80 + ks * 32 + c * 4;
                bf[j][0] = lds_u32(Xs + off);
                bf[j][1] = lds_u32(Xs + off + 16);
            }
            #pragma unroll
            for (int i = 0; i < 4; i++)
                #pragma unroll
                for (int j = 0; j < 4; j++)
                    mma_f16(acc[i][j], af[i], bf[j]);
        }
        __syncthreads();
    }

    const int mt = blockIdx.y * 2 + (wv >> 1);
    uint32_t* base = g_Vh + ((size_t)b * 64 + mt) * 16384;
    #pragma unroll
    for (int i = 0; i < 4; i++) {
        const int vg = v0 + wn * 64 + i * 16 + g;
        const float sg = g_scl[vg],     hg = g_shf[vg];
        const float s8 = g_scl[vg + 8], h8 = g_shf[vg + 8];
        const int vj = vg >> 3;
        #pragma unroll
        for (int j = 0; j < 4; j++) {
            const int kb = ((wv * 32 + j * 8) >> 4) & 3;
            const int lohi = j & 1;
            __half a0 = __float2half(fmaxf(fmaf(acc[i][j][0], sg, hg), 0.f));
            __half a1 = __float2half(fmaxf(fmaf(acc[i][j][1], sg, hg), 0.f));
            __half a2 = __float2half(fmaxf(fmaf(acc[i][j][2], s8, h8), 0.f));
            __half a3 = __float2half(fmaxf(fmaf(acc[i][j][3], s8, h8), 0.f));
            base[(size_t)kb * 4096 + (size_t)vj * 64 + lane * 2 + lohi]       = hfcat(a0, a1);
            base[(size_t)kb * 4096 + (size_t)(vj + 1) * 64 + lane * 2 + lohi] = hfcat(a2, a3);
        }
    }
}

// ===========================================================================
// Energy, FUSED max pass (phase 1: 128-row K-hi chunks) + 3-term energy.
// grid (Nn/64, 4), b = b0 + blockIdx.y.   (math identical to R16)
// ===========================================================================
static constexpr int E_QH  = 0;
static constexpr int E_QL  = 9216;
static constexpr int E_KH0 = 18432;
static constexpr int E_KH1 = 27648;
static constexpr int E_KL0 = 36864;
static constexpr int E_KL1 = 46080;
static constexpr int E_BYTES = 55296;

__device__ __forceinline__ void e_stage128(uint32_t sbase, int par, size_t koff, int base) {
    const int t = threadIdx.x;
    const uint32_t kh = sbase + (par ? E_KH1 : E_KH0);
    const uint32_t kl = sbase + (par ? E_KL1 : E_KL0);
    #pragma unroll
    for (int p = 0; p < 4; p++) {
        int id = t + 256 * p, r = id >> 3, c8 = id & 7;
        uint32_t dst = (r < 64 ? kh + r * 144 : kl + (r - 64) * 144) + c8 * 16;
        cp_async16(dst, g_Kh + koff + (size_t)(base + r) * Kd + c8 * 8);
    }
}

__global__ __launch_bounds__(256) void energy_mma_kernel(int b0) {
    extern __shared__ char smc[];
    __shared__ float sR[4][64];
    const uint32_t sbase = smem_u32(smc);
    const int tid = threadIdx.x;
    const int wid = tid >> 5, lane = tid & 31;
    const int g = lane >> 2, c = lane & 3;
    const int wn = wid & 1, wv = wid >> 1;
    const int b  = b0 + blockIdx.y;
    const int n0 = blockIdx.x * 64;
    const int nt = blockIdx.x >> 1;
    const int half = blockIdx.x & 1;

    const size_t qoff = ((size_t)b * Nn + n0) * Kd;
    const size_t koff = (size_t)b * Nn * Kd;

    #pragma unroll
    for (int p = 0; p < 2; p++) {
        int id = tid + 256 * p, r = id >> 3, c8 = id & 7;
        cp_async16(sbase + E_QH + r * 144 + c8 * 16, g_Qh + qoff + (size_t)r * Kd + c8 * 8);
        cp_async16(sbase + E_QL + r * 144 + c8 * 16, g_Ql + qoff + (size_t)r * Kd + c8 * 8);
    }
    e_stage128(sbase, 0, koff, 0);
    cp_commit();

    // =============== Phase 1: exact row max (hi-only), 128-row chunks ======
    float mx[2][2] = { { -1e30f, -1e30f }, { -1e30f, -1e30f } };

    for (int mc2 = 0; mc2 < 32; mc2++) {
        const int cur = mc2 & 1;
        if (mc2 + 1 < 32) {
            e_stage128(sbase, cur ^ 1, koff, (mc2 + 1) * 128);
            cp_commit();
            cp_wait1();
        } else {
            cp_wait0();
        }
        __syncthreads();

        const char* QH = smc + E_QH;
        const char* KA = smc + (cur ? E_KH1 : E_KH0);
        const char* KB = smc + (cur ? E_KL1 : E_KL0);

        float acc[2][4][4] = {};
        #pragma unroll
        for (int ks = 0; ks < 4; ks++) {
            uint32_t ah[2][4];
            #pragma unroll
            for (int i = 0; i < 2; i++) {
                const int off = (wn * 32 + i * 16 + g) * 144 + ks * 32 + c * 4;
                ah[i][0] = lds_u32(QH + off);
                ah[i][1] = lds_u32(QH + off + 8 * 144);
                ah[i][2] = lds_u32(QH + off + 16);
                ah[i][3] = lds_u32(QH + off + 8 * 144 + 16);
            }
            uint32_t bh[4][2];
            #pragma unroll
            for (int j = 0; j < 2; j++) {
                const int off = (wv * 16 + j * 8 + g) * 144 + ks * 32 + c * 4;
                bh[j][0]     = lds_u32(KA + off);
                bh[j][1]     = lds_u32(KA + off + 16);
                bh[j + 2][0] = lds_u32(KB + off);
                bh[j + 2][1] = lds_u32(KB + off + 16);
            }
            #pragma unroll
            for (int i = 0; i < 2; i++)
                #pragma unroll
                for (int j = 0; j < 4; j++)
                    mma_bf16(acc[i][j], ah[i], bh[j]);
        }
        __syncthreads();

        #pragma unroll
        for (int i = 0; i < 2; i++)
            #pragma unroll
            for (int j = 0; j < 4; j++) {
                mx[i][0] = fmaxf(mx[i][0], fmaxf(acc[i][j][0], acc[i][j][1]));
                mx[i][1] = fmaxf(mx[i][1], fmaxf(acc[i][j][2], acc[i][j][3]));
            }
    }

    #pragma unroll
    for (int i = 0; i < 2; i++)
        #pragma unroll
        for (int r = 0; r < 2; r++) {
            float v = mx[i][r];
            v = fmaxf(v, __shfl_xor_sync(0xffffffffu, v, 1));
            v = fmaxf(v, __shfl_xor_sync(0xffffffffu, v, 2));
            mx[i][r] = v;
        }
    if (c == 0) {
        #pragma unroll
        for (int i = 0; i < 2; i++) {
            sR[wv][wn * 32 + i * 16 + g]     = mx[i][0];
            sR[wv][wn * 32 + i * 16 + g + 8] = mx[i][1];
        }
    }
    __syncthreads();

    float Mv[2][2];
    #pragma unroll
    for (int i = 0; i < 2; i++) {
        const int r0 = wn * 32 + i * 16 + g;
        Mv[i][0] = fmaxf(fmaxf(sR[0][r0],     sR[1][r0]),     fmaxf(sR[2][r0],     sR[3][r0]));
        Mv[i][1] = fmaxf(fmaxf(sR[0][r0 + 8], sR[1][r0 + 8]), fmaxf(sR[2][r0 + 8], sR[3][r0 + 8]));
    }
    __syncthreads();

    // =============== Phase 2: full 3-term energy + exp ===============
    #pragma unroll
    for (int p = 0; p < 2; p++) {
        int id = tid + 256 * p, r = id >> 3, c8 = id & 7;
        cp_async16(sbase + E_KH0 + r * 144 + c8 * 16, g_Kh + koff + (size_t)r * Kd + c8 * 8);
        cp_async16(sbase + E_KL0 + r * 144 + c8 * 16, g_Kl + koff + (size_t)r * Kd + c8 * 8);
    }
    cp_commit();

    float rsum[2][2] = {};

    for (int mc = 0; mc < 64; mc++) {
        const int cur = mc & 1;
        if (mc + 1 < 64) {
            const uint32_t kh = sbase + ((mc + 1) & 1 ? E_KH1 : E_KH0);
            const uint32_t kl = sbase + ((mc + 1) & 1 ? E_KL1 : E_KL0);
            #pragma unroll
            for (int p = 0; p < 2; p++) {
                int id = tid + 256 * p, r = id >> 3, c8 = id & 7;
                cp_async16(kh + r * 144 + c8 * 16,
                           g_Kh + koff + (size_t)((mc + 1) * 64 + r) * Kd + c8 * 8);
                cp_async16(kl + r * 144 + c8 * 16,
                           g_Kl + koff + (size_t)((mc + 1) * 64 + r) * Kd + c8 * 8);
            }
            cp_commit();
            cp_wait1();
        } else {
            cp_wait0();
        }
        __syncthreads();

        const char* QH = smc + E_QH;
        const char* QL = smc + E_QL;
        const char* KH = smc + (cur ? E_KH1 : E_KH0);
        const char* KL = smc + (cur ? E_KL1 : E_KL0);

        float acc[2][2][4] = {};
        #pragma unroll
        for (int ks = 0; ks < 4; ks++) {
            uint32_t ah[2][4], al[2][4];
            #pragma unroll
            for (int i = 0; i < 2; i++) {
                const int off = (wn * 32 + i * 16 + g) * 144 + ks * 32 + c * 4;
                ah[i][0] = lds_u32(QH + off);
                ah[i][1] = lds_u32(QH + off + 8 * 144);
                ah[i][2] = lds_u32(QH + off + 16);
                ah[i][3] = lds_u32(QH + off + 8 * 144 + 16);
                al[i][0] = lds_u32(QL + off);
                al[i][1] = lds_u32(QL + off + 8 * 144);
                al[i][2] = lds_u32(QL + off + 16);
                al[i][3] = lds_u32(QL + off + 8 * 144 + 16);
            }
            uint32_t bh[2][2], bl[2][2];
            #pragma unroll
            for (int j = 0; j < 2; j++) {
                const int off = (wv * 16 + j * 8 + g) * 144 + ks * 32 + c * 4;
                bh[j][0] = lds_u32(KH + off);
                bh[j][1] = lds_u32(KH + off + 16);
                bl[j][0] = lds_u32(KL + off);
                bl[j][1] = lds_u32(KL + off + 16);
            }
            #pragma unroll
            for (int i = 0; i < 2; i++)
                #pragma unroll
                for (int j = 0; j < 2; j++) {
                    mma_bf16(acc[i][j], ah[i], bh[j]);
                    mma_bf16(acc[i][j], ah[i], bl[j]);
                    mma_bf16(acc[i][j], al[i], bh[j]);
                }
        }
        __syncthreads();

        const size_t tile0 = (((size_t)b * 32 + nt) * 64 + mc) * 4096;
        #pragma unroll
        for (int i = 0; i < 2; i++) {
            const int i_blk = half * 4 + wn * 2 + i;
            __half h[2][4];
            #pragma unroll
            for (int j = 0; j < 2; j++) {
                h[j][0] = __float2half(__expf(acc[i][j][0] - Mv[i][0]));
                h[j][1] = __float2half(__expf(acc[i][j][1] - Mv[i][0]));
                h[j][2] = __float2half(__expf(acc[i][j][2] - Mv[i][1]));
                h[j][3] = __float2half(__expf(acc[i][j][3] - Mv[i][1]));
                rsum[i][0] += __half2float(h[j][0]) + __half2float(h[j][1]);
                rsum[i][1] += __half2float(h[j][2]) + __half2float(h[j][3]);
            }
            uint4 w4;
            w4.x = hfcat(h[0][0], h[0][1]);
            w4.y = hfcat(h[0][2], h[0][3]);
            w4.z = hfcat(h[1][0], h[1][1]);
            w4.w = hfcat(h[1][2], h[1][3]);
            *(uint4*)&g_Pf[tile0 + (size_t)((i_blk * 4 + wv) * 128 + lane * 4)] = w4;
        }
    }

    #pragma unroll
    for (int i = 0; i < 2; i++)
        #pragma unroll
        for (int r = 0; r < 2; r++) {
            float v = rsum[i][r];
            v += __shfl_xor_sync(0xffffffffu, v, 1);
            v += __shfl_xor_sync(0xffffffffu, v, 2);
            rsum[i][r] = v;
        }
    if (c == 0) {
        #pragma unroll
        for (int i = 0; i < 2; i++) {
            sR[wv][wn * 32 + i * 16 + g]     = rsum[i][0];
            sR[wv][wn * 32 + i * 16 + g + 8] = rsum[i][1];
        }
    }
    __syncthreads();
    if (tid < 64)
        g_L[(size_t)b * Nn + n0 + tid] = sR[0][tid] + sR[1][tid] + sR[2][tid] + sR[3][tid];
}

// ===========================================================================
// PV GEMM on fp16 m16n8k16, packed fragments, K-chunk 64, 3-STAGE pipeline.
// grid (4, 32, 4), b = b0 + blockIdx.z.   (math identical to R16)
// ===========================================================================
static constexpr int AV_BYTES = 98304;

__device__ __forceinline__ void av_stage(uint32_t sbase, int s,
                                         const uint32_t* gA, const uint32_t* gB,
                                         int v0j, int mt) {
    const int t = threadIdx.x;
    const uint32_t sA = sbase + (uint32_t)(s * 4096) * 4;
    const uint32_t sB = sbase + (uint32_t)(12288 + s * 4096) * 4;
    const uint32_t* gAt = gA + (size_t)mt * 4096;
    const uint32_t* gBt = gB + (size_t)mt * 16384 + (size_t)v0j * 64;
    #pragma unroll
    for (int p = 0; p < 4; p++) {
        int id = t + 256 * p;
        cp_async16(sA + (uint32_t)id * 16, gAt + id * 4);
    }
    #pragma unroll
    for (int p = 0; p < 4; p++) {
        int id = t + 256 * p, kb = id >> 8, rem = id & 255;
        int vjl = rem >> 4, q = rem & 15;
        cp_async16(sB + (uint32_t)(kb * 1024 + vjl * 64 + q * 4) * 4,
                   gBt + (size_t)kb * 4096 + (size_t)vjl * 64 + q * 4);
    }
}

__global__ __launch_bounds__(256, 2) void av_mma_kernel(float* __restrict__ out, int b0) {
    extern __shared__ uint32_t smu[];
    const uint32_t sbase = smem_u32(smu);
    const int tid  = threadIdx.x;
    const int wid  = tid >> 5, lane = tid & 31;
    const int g = lane >> 2, c = lane & 3;
    const int wn = wid & 1, wv = wid >> 1;
    const int b  = b0 + blockIdx.z;
    const int nt = blockIdx.y;
    const int n0 = nt * 128;
    const int v0 = blockIdx.x * 128;

    const uint32_t* gA = g_Pf + (((size_t)b * 32 + nt) * 64) * 4096;
    const uint32_t* gB = g_Vh + ((size_t)b * 64) * 16384;

    float acc[4][4][4] = {};

    av_stage(sbase, 0, gA, gB, v0 >> 3, 0); cp_commit();
    av_stage(sbase, 1, gA, gB, v0 >> 3, 1); cp_commit();

    for (int mt = 0; mt < 64; mt++) {
        const int s = mt % 3;
        if (mt + 2 < 64) {
            av_stage(sbase, (mt + 2) % 3, gA, gB, v0 >> 3, mt + 2);
            cp_commit();
            cp_wait2();
        } else if (mt + 1 < 64) {
            cp_wait1();
        } else {
            cp_wait0();
        }
        __syncthreads();

        const uint32_t* As = smu + s * 4096;
        const uint32_t* Bs = smu + 12288 + s * 4096;

        #pragma unroll
        for (int kb = 0; kb < 4; kb++) {
            uint4 af[4];
            #pragma unroll
            for (int i = 0; i < 4; i++)
                af[i] = *(const uint4*)(As + (wn * 4 + i) * 512 + kb * 128 + lane * 4);
            uint2 bfr[4];
            #pragma unroll
            for (int j = 0; j < 4; j++)
                bfr[j] = *(const uint2*)(Bs + kb * 1024 + (wv * 4 + j) * 64 + lane * 2);
            #pragma unroll
            for (int i = 0; i < 4; i++)
                #pragma unroll
                for (int j = 0; j < 4; j++)
                    mma_f16(acc[i][j], (const uint32_t*)&af[i], (const uint32_t*)&bfr[j]);
        }
        __syncthreads();
    }

    #pragma unroll
    for (int i = 0; i < 4; i++) {
        const int n_lo = n0 + wn * 64 + i * 16 + g;
        const float linv_lo = 1.0f / g_L[(size_t)b * Nn + n_lo];
        const float linv_hi = 1.0f / g_L[(size_t)b * Nn + n_lo + 8];
        #pragma unroll
        for (int j = 0; j < 4; j++) {
            const int v = v0 + wv * 32 + j * 8 + c * 2;
            float* o0p = out + ((size_t)b * Vd + v)     * Nn + n_lo;
            float* o1p = out + ((size_t)b * Vd + v + 1) * Nn + n_lo;
            o0p[0] = acc[i][j][0] * linv_lo;
            o1p[0] = acc[i][j][1] * linv_lo;
            o0p[8] = acc[i][j][2] * linv_hi;
            o1p[8] = acc[i][j][3] * linv_hi;
        }
    }
}

// ===========================================================================
// Launch: batch-halved pipelined graph.
//   s0: prep_all -> xsplit -> qk -> energy03 -> energy47 -> (wait vp) av47
//   s2: (wait x) vproj -> (wait e03) av03 -> join back to s0
// ===========================================================================
extern "C" void kernel_launch(void* const* d_in, const int* in_sizes, int n_in,
                              void* d_out, int out_size) {
    const float* x     = (const float*)d_in[0];
    const float* Wq    = (const float*)d_in[1];
    const float* bq    = (const float*)d_in[2];
    const float* Wk    = (const float*)d_in[3];
    const float* bk    = (const float*)d_in[4];
    const float* Wv    = (const float*)d_in[5];
    const float* gamma = (const float*)d_in[6];
    const float* beta  = (const float*)d_in[7];
    const float* mean  = (const float*)d_in[8];
    const float* var   = (const float*)d_in[9];
    float* out = (float*)d_out;

    static cudaStream_t s2 = nullptr;
    static cudaEvent_t ev_x = nullptr, ev_vp = nullptr, ev_e1 = nullptr, ev_join = nullptr;
    static int inited = 0;
    if (!inited) {
        cudaFuncSetAttribute(qk_mma_kernel,
                             cudaFuncAttributeMaxDynamicSharedMemorySize, QK_BYTES);
        cudaFuncSetAttribute(vproj_mma_kernel,
                             cudaFuncAttributeMaxDynamicSharedMemorySize, VP_BYTES);
        cudaFuncSetAttribute(energy_mma_kernel,
                             cudaFuncAttributeMaxDynamicSharedMemorySize, E_BYTES);
        cudaFuncSetAttribute(av_mma_kernel,
                             cudaFuncAttributeMaxDynamicSharedMemorySize, AV_BYTES);
        cudaStreamCreateWithFlags(&s2, cudaStreamNonBlocking);
        cudaEventCreateWithFlags(&ev_x,    cudaEventDisableTiming);
        cudaEventCreateWithFlags(&ev_vp,   cudaEventDisableTiming);
        cudaEventCreateWithFlags(&ev_e1,   cudaEventDisableTiming);
        cudaEventCreateWithFlags(&ev_join, cudaEventDisableTiming);
        inited = 1;
    }

    // s0: preprocessing
    prep_all_kernel<<<1024, 256>>>(gamma, beta, mean, var, Wq, Wk, Wv);
    xsplit_kernel<<<dim3(Nn / 32, Cc / 32, Bn), 256>>>(x);
    cudaEventRecord(ev_x, 0);

    // s2: vproj (needs xsplit + prep_all, both before ev_x on s0)
    cudaStreamWaitEvent(s2, ev_x, 0);
    vproj_mma_kernel<<<dim3(Vd / 128, Nn / 128, Bn), 256, VP_BYTES, s2>>>();
    cudaEventRecord(ev_vp, s2);

    // s0: qk -> energy batches 0-3 -> energy batches 4-7
    qk_mma_kernel<<<dim3(Nn / 64, 1, Bn), 256, QK_BYTES>>>(bq, bk);
    energy_mma_kernel<<<dim3(Nn / 64, 4), 256, E_BYTES>>>(0);
    cudaEventRecord(ev_e1, 0);
    energy_mma_kernel<<<dim3(Nn / 64, 4), 256, E_BYTES>>>(4);

    // s2: av batches 0-3 (after energy03 + vproj)
    cudaStreamWaitEvent(s2, ev_e1, 0);
    av_mma_kernel<<<dim3(Vd / 128, Nn / 128, 4), 256, AV_BYTES, s2>>>(out, 0);
    cudaEventRecord(ev_join, s2);

    // s0: av batches 4-7 (after energy47 in program order + vproj)
    cudaStreamWaitEvent(0, ev_vp, 0);
    av_mma_kernel<<<dim3(Vd / 128, Nn / 128, 4), 256, AV_BYTES>>>(out, 4);

    // join s2 back into s0 before capture ends
    cudaStreamWaitEvent(0, ev_join, 0);
}